// round 10
// baseline (speedup 1.0000x reference)
#include <cuda_runtime.h>
#include <cuda_bf16.h>
#include <cstdint>

#define BATCH 16
#define CDIM  256
#define NPIX  4096
#define O3    768
#define HEADS 4
#define DH    64
#define NSPL  16

// ------------------------- scratch ------------------------------------------
__device__ __nv_bfloat16 g_wb  [O3 * CDIM];                       // w_qkv bf16
__device__ __nv_bfloat16 g_qkvb[(size_t)BATCH * O3 * NPIX];       // qkv  [b][o][n]
__device__ float2        g_kstat[BATCH * 256];                    // {max, 1/sum} per K row
__device__ float         g_ctxp[BATCH * HEADS * NSPL * DH * DH];  // ctx partials (raw exp sums)
__device__ __nv_bfloat16 g_weff[BATCH * CDIM * CDIM];             // Weff [b][o][hd]

// ------------------------- mma helpers --------------------------------------
__device__ __forceinline__ uint32_t cvta_s(const void* p) {
    return (uint32_t)__cvta_generic_to_shared(p);
}
__device__ __forceinline__ void ldsm4(uint32_t* r, uint32_t a) {
    asm volatile("ldmatrix.sync.aligned.m8n8.x4.shared.b16 {%0,%1,%2,%3},[%4];"
                 : "=r"(r[0]), "=r"(r[1]), "=r"(r[2]), "=r"(r[3]) : "r"(a));
}
__device__ __forceinline__ void ldsm4t(uint32_t* r, uint32_t a) {
    asm volatile("ldmatrix.sync.aligned.m8n8.x4.trans.shared.b16 {%0,%1,%2,%3},[%4];"
                 : "=r"(r[0]), "=r"(r[1]), "=r"(r[2]), "=r"(r[3]) : "r"(a));
}
__device__ __forceinline__ void mma16816(float* d, const uint32_t* a, const uint32_t* b) {
    asm volatile(
        "mma.sync.aligned.m16n8k16.row.col.f32.bf16.bf16.f32 "
        "{%0,%1,%2,%3},{%4,%5,%6,%7},{%8,%9},{%0,%1,%2,%3};"
        : "+f"(d[0]), "+f"(d[1]), "+f"(d[2]), "+f"(d[3])
        : "r"(a[0]), "r"(a[1]), "r"(a[2]), "r"(a[3]), "r"(b[0]), "r"(b[1]));
}
__device__ __forceinline__ uint4 cvt8_bf16(float4 lo, float4 hi) {
    __nv_bfloat162 p0 = __floats2bfloat162_rn(lo.x, lo.y);
    __nv_bfloat162 p1 = __floats2bfloat162_rn(lo.z, lo.w);
    __nv_bfloat162 p2 = __floats2bfloat162_rn(hi.x, hi.y);
    __nv_bfloat162 p3 = __floats2bfloat162_rn(hi.z, hi.w);
    uint4 r;
    r.x = *(uint32_t*)&p0; r.y = *(uint32_t*)&p1;
    r.z = *(uint32_t*)&p2; r.w = *(uint32_t*)&p3;
    return r;
}
__device__ __forceinline__ uint32_t exp_bf162(uint32_t wv, float mx) {
    __nv_bfloat162 h = *(__nv_bfloat162*)&wv;
    __nv_bfloat162 r = __floats2bfloat162_rn(__expf(__low2float(h) - mx),
                                             __expf(__high2float(h) - mx));
    return *(uint32_t*)&r;
}
__device__ __forceinline__ uint4 exp_u4(uint4 v, float mx) {
    uint4 r;
    r.x = exp_bf162(v.x, mx); r.y = exp_bf162(v.y, mx);
    r.z = exp_bf162(v.z, mx); r.w = exp_bf162(v.w, mx);
    return r;
}

// ============================================================================
// bf16 HMMA GEMM:  C[b][M][4096] = A[b][M][256] @ B[b][256][4096]
//   BM=256, BN=64, BK=32.  256 thr = 8 warps (4x2), warp tile 64x32.
//   A: [M][256] bf16 K-major.  B: natural [K][N]; bf16 (BF32=0) or f32 with
//   on-the-fly convert (BF32=1); trans-ldmatrix from XOR-swizzled smem.
//   Double-buffered smem + register prefetch.
// EPI 0: bf16 out.  EPI 1: y = gamma[m]*(acc+bias[m]) + x  (fp32)
// ============================================================================
template <int EPI, int BF32>
__global__ void __launch_bounds__(256, 2)
gemm_mma(const __nv_bfloat16* __restrict__ A, long strideA,
         const __nv_bfloat16* __restrict__ Bb16, const float* __restrict__ Bf32,
         long strideB,
         float* __restrict__ outf, __nv_bfloat16* __restrict__ outb,
         long strideC,
         const float* __restrict__ bias, const float* __restrict__ gamma,
         const float* __restrict__ xres)
{
    __shared__ __nv_bfloat16 As[2][256][40];   // padded rows (80B, 16B-aligned)
    __shared__ __nv_bfloat16 Bs[2][32][64];    // XOR-swizzled (ngrp ^ (k&7))

    const int t = threadIdx.x, lane = t & 31, w = t >> 5;
    const int wm = w >> 1, wn = w & 1;
    const int b = blockIdx.z, m0 = blockIdx.y * 256, n0 = blockIdx.x * 64;

    const __nv_bfloat16* Ab = A + (size_t)b * strideA;
    const __nv_bfloat16* Bb = BF32 ? nullptr : (Bb16 + (size_t)b * strideB);
    const float*         Bf = BF32 ? (Bf32 + (size_t)b * strideB) : nullptr;

    float acc[4][4][4];
    #pragma unroll
    for (int i = 0; i < 4; i++)
        #pragma unroll
        for (int j = 0; j < 4; j++)
            #pragma unroll
            for (int c = 0; c < 4; c++) acc[i][j][c] = 0.f;

    // ---- staging coords ----
    const int arow = t >> 2, acol = (t & 3) * 8;        // A: rows arow+64*i
    const int bk = t >> 3, bg = t & 7;                  // B: row bk, group bg
    const int bph = (bg ^ (bk & 7)) * 8;                // swizzled col (elems)

    // ---- fragment source addresses ----
    const int a_row = (lane & 7) + 8 * ((lane >> 3) & 1);
    const int a_kad = 8 * (lane >> 4);
    const int b_krow = lane & 15;
    const int b_nsub = lane >> 4;

    uint4 pa[4], pb;

    // stage 0
    #pragma unroll
    for (int i = 0; i < 4; i++)
        *(uint4*)&As[0][arow + 64 * i][acol] =
            *(const uint4*)(Ab + (size_t)(m0 + arow + 64 * i) * CDIM + acol);
    if (BF32) {
        const float* r0 = Bf + (size_t)bk * NPIX + n0 + bg * 8;
        pb = cvt8_bf16(*(const float4*)r0, *(const float4*)(r0 + 4));
    } else {
        pb = *(const uint4*)(Bb + (size_t)bk * NPIX + n0 + bg * 8);
    }
    *(uint4*)&Bs[0][bk][bph] = pb;
    __syncthreads();

    const int KT = CDIM / 32;
    #pragma unroll 1
    for (int it = 0; it < KT; it++) {
        const int cur = it & 1, nxt = cur ^ 1;
        const int kN = (it + 1) * 32;
        if (it + 1 < KT) {
            #pragma unroll
            for (int i = 0; i < 4; i++)
                pa[i] = *(const uint4*)(Ab + (size_t)(m0 + arow + 64 * i) * CDIM + kN + acol);
            if (BF32) {
                const float* r0 = Bf + (size_t)(kN + bk) * NPIX + n0 + bg * 8;
                pb = cvt8_bf16(*(const float4*)r0, *(const float4*)(r0 + 4));
            } else {
                pb = *(const uint4*)(Bb + (size_t)(kN + bk) * NPIX + n0 + bg * 8);
            }
        }

        #pragma unroll
        for (int ki = 0; ki < 32; ki += 16) {
            uint32_t af[4][4], bfr[2][4];
            #pragma unroll
            for (int mi = 0; mi < 4; mi++)
                ldsm4(af[mi], cvta_s(&As[cur][wm * 64 + mi * 16 + a_row][ki + a_kad]));
            #pragma unroll
            for (int n2 = 0; n2 < 2; n2++) {
                int krow = ki + b_krow;
                int glog = wn * 4 + n2 * 2 + b_nsub;
                int gphy = glog ^ (krow & 7);
                ldsm4t(bfr[n2], cvta_s(&Bs[cur][krow][gphy * 8]));
            }
            #pragma unroll
            for (int mi = 0; mi < 4; mi++)
                #pragma unroll
                for (int nj = 0; nj < 4; nj++)
                    mma16816(acc[mi][nj], af[mi], &bfr[nj >> 1][(nj & 1) * 2]);
        }

        if (it + 1 < KT) {
            #pragma unroll
            for (int i = 0; i < 4; i++)
                *(uint4*)&As[nxt][arow + 64 * i][acol] = pa[i];
            *(uint4*)&Bs[nxt][bk][bph] = pb;
        }
        __syncthreads();
    }

    const int gid = lane >> 2, tig = lane & 3;
    #pragma unroll
    for (int mi = 0; mi < 4; mi++) {
        int m = m0 + wm * 64 + mi * 16 + gid;
        if (EPI == 0) {
            __nv_bfloat16* C0 = outb + (size_t)b * strideC + (size_t)m * NPIX;
            __nv_bfloat16* C1 = C0 + 8 * NPIX;
            #pragma unroll
            for (int nj = 0; nj < 4; nj++) {
                int n = n0 + wn * 32 + nj * 8 + tig * 2;
                __nv_bfloat162 lo = __floats2bfloat162_rn(acc[mi][nj][0], acc[mi][nj][1]);
                __nv_bfloat162 hi = __floats2bfloat162_rn(acc[mi][nj][2], acc[mi][nj][3]);
                *(__nv_bfloat162*)(C0 + n) = lo;
                *(__nv_bfloat162*)(C1 + n) = hi;
            }
        } else {
            const float g0 = gamma[m], g1 = gamma[m + 8];
            const float bo0 = bias[m], bo1 = bias[m + 8];
            float*       C0 = outf + (size_t)b * strideC + (size_t)m * NPIX;
            float*       C1 = C0 + 8 * NPIX;
            const float* X0 = xres + (size_t)b * strideC + (size_t)m * NPIX;
            const float* X1 = X0 + 8 * NPIX;
            #pragma unroll
            for (int nj = 0; nj < 4; nj++) {
                int n = n0 + wn * 32 + nj * 8 + tig * 2;
                float2 x0 = *(const float2*)(X0 + n);
                float2 x1 = *(const float2*)(X1 + n);
                float2 o0, o1;
                o0.x = fmaf(g0, acc[mi][nj][0] + bo0, x0.x);
                o0.y = fmaf(g0, acc[mi][nj][1] + bo0, x0.y);
                o1.x = fmaf(g1, acc[mi][nj][2] + bo1, x1.x);
                o1.y = fmaf(g1, acc[mi][nj][3] + bo1, x1.y);
                *(float2*)(C0 + n) = o0;
                *(float2*)(C1 + n) = o1;
            }
        }
    }
}

// ============================================================================
// K row stats: per row (b, hd): mx = max_n k, inv = 1/sum_n exp(k - mx)
// ============================================================================
__global__ __launch_bounds__(256)
void k_stat(const __nv_bfloat16* __restrict__ qkv, float2* __restrict__ stat)
{
    int r = blockIdx.x, b = r >> 8, hd = r & 255;
    const uint4* row4 = (const uint4*)(qkv + ((size_t)b * O3 + 256 + hd) * NPIX);
    int t = threadIdx.x;

    uint4 u0 = row4[t * 2], u1 = row4[t * 2 + 1];
    uint32_t wd[8] = { u0.x, u0.y, u0.z, u0.w, u1.x, u1.y, u1.z, u1.w };
    float f[16];
    #pragma unroll
    for (int i = 0; i < 8; i++) {
        __nv_bfloat162 h = *(__nv_bfloat162*)&wd[i];
        f[2 * i]     = __low2float(h);
        f[2 * i + 1] = __high2float(h);
    }

    float mx = -3.4e38f;
    #pragma unroll
    for (int i = 0; i < 16; i++) mx = fmaxf(mx, f[i]);

    __shared__ float sred[8];
    int lane = t & 31, wr = t >> 5;
    #pragma unroll
    for (int o = 16; o; o >>= 1) mx = fmaxf(mx, __shfl_xor_sync(~0u, mx, o));
    if (lane == 0) sred[wr] = mx;
    __syncthreads();
    if (t < 8) {
        float m2 = sred[t];
        #pragma unroll
        for (int o = 4; o; o >>= 1) m2 = fmaxf(m2, __shfl_xor_sync(0xffu, m2, o));
        if (t == 0) sred[0] = m2;
    }
    __syncthreads();
    mx = sred[0];
    __syncthreads();

    float sum = 0.f;
    #pragma unroll
    for (int i = 0; i < 16; i++) sum += __expf(f[i] - mx);
    #pragma unroll
    for (int o = 16; o; o >>= 1) sum += __shfl_xor_sync(~0u, sum, o);
    if (lane == 0) sred[wr] = sum;
    __syncthreads();
    if (t < 8) {
        float s2 = sred[t];
        #pragma unroll
        for (int o = 4; o; o >>= 1) s2 += __shfl_xor_sync(0xffu, s2, o);
        if (t == 0) stat[r] = make_float2(mx, 1.0f / s2);
    }
}

// ============================================================================
// ctx partial (fused exp): ctxp[b,h,s][d][e] = sum_{n in split} exp(K[d,n]-mx[d]) * V[e,n]
// NSPL=16 (256 n per split), BK=64, double-buffered, 128 thr (4 warps 2x2).
// Staging: 4 uint4 per thread covers the 64x64 tile exactly.
// ============================================================================
__global__ void __launch_bounds__(128)
ctx_mma(const __nv_bfloat16* __restrict__ qkv, const float2* __restrict__ stat,
        float* __restrict__ ctxp)
{
    __shared__ __nv_bfloat16 Ks[2][64][72];
    __shared__ __nv_bfloat16 Vs[2][64][72];

    const int s = blockIdx.x, h = blockIdx.y, b = blockIdx.z;
    const int t = threadIdx.x, lane = t & 31, w = t >> 5;
    const int wm = w >> 1, wn = w & 1;
    const int NPER = NPIX / NSPL;       // 256

    const __nv_bfloat16* kb = qkv + ((size_t)b * O3 + 256 + h * DH) * NPIX + s * NPER;
    const __nv_bfloat16* vb = qkv + ((size_t)b * O3 + 512 + h * DH) * NPIX + s * NPER;

    // staging: i in 0..3, row = (i*128+t)>>3 (0..63), col = (t&7)*8
    const int scol = (t & 7) * 8;
    int   srow[4];
    float mxv[4];
    #pragma unroll
    for (int i = 0; i < 4; i++) {
        srow[i] = (i * 128 + t) >> 3;
        mxv[i]  = stat[b * 256 + h * DH + srow[i]].x;
    }

    float acc[2][4][4];
    #pragma unroll
    for (int i = 0; i < 2; i++)
        #pragma unroll
        for (int j = 0; j < 4; j++)
            #pragma unroll
            for (int c = 0; c < 4; c++) acc[i][j][c] = 0.f;

    const int a_row = (lane & 7) + 8 * ((lane >> 3) & 1);
    const int a_kad = 8 * (lane >> 4);
    const int b_row = (lane & 7) + 8 * ((lane >> 4) & 1);
    const int b_kad = 8 * ((lane >> 3) & 1);

    uint4 rk[4], rv[4];

    // stage 0
    #pragma unroll
    for (int i = 0; i < 4; i++) {
        uint4 kv = *(const uint4*)(kb + (size_t)srow[i] * NPIX + scol);
        *(uint4*)&Ks[0][srow[i]][scol] = exp_u4(kv, mxv[i]);
        *(uint4*)&Vs[0][srow[i]][scol] = *(const uint4*)(vb + (size_t)srow[i] * NPIX + scol);
    }
    __syncthreads();

    const int IT = NPER / 64;           // 4
    #pragma unroll 1
    for (int it = 0; it < IT; it++) {
        const int cur = it & 1, nxt = cur ^ 1;
        const int kN = (it + 1) * 64;
        if (it + 1 < IT) {
            #pragma unroll
            for (int i = 0; i < 4; i++) {
                rk[i] = *(const uint4*)(kb + (size_t)srow[i] * NPIX + kN + scol);
                rv[i] = *(const uint4*)(vb + (size_t)srow[i] * NPIX + kN + scol);
            }
        }

        #pragma unroll
        for (int ki = 0; ki < 64; ki += 16) {
            uint32_t af[2][4], bfr[2][4];
            #pragma unroll
            for (int mi = 0; mi < 2; mi++)
                ldsm4(af[mi], cvta_s(&Ks[cur][wm * 32 + mi * 16 + a_row][ki + a_kad]));
            #pragma unroll
            for (int n2 = 0; n2 < 2; n2++)
                ldsm4(bfr[n2], cvta_s(&Vs[cur][wn * 32 + n2 * 16 + b_row][ki + b_kad]));
            #pragma unroll
            for (int mi = 0; mi < 2; mi++)
                #pragma unroll
                for (int nj = 0; nj < 4; nj++)
                    mma16816(acc[mi][nj], af[mi], &bfr[nj >> 1][(nj & 1) * 2]);
        }

        if (it + 1 < IT) {
            #pragma unroll
            for (int i = 0; i < 4; i++) {
                *(uint4*)&Ks[nxt][srow[i]][scol] = exp_u4(rk[i], mxv[i]);
                *(uint4*)&Vs[nxt][srow[i]][scol] = rv[i];
            }
        }
        __syncthreads();
    }

    const int gid = lane >> 2, tig = lane & 3;
    float* dst = ctxp + (((size_t)(b * HEADS + h) * NSPL + s)) * (DH * DH);
    #pragma unroll
    for (int mi = 0; mi < 2; mi++) {
        int d = wm * 32 + mi * 16 + gid;
        #pragma unroll
        for (int nj = 0; nj < 4; nj++) {
            int e = wn * 32 + nj * 8 + tig * 2;
            *(float2*)(dst + (size_t)d * DH + e)       = make_float2(acc[mi][nj][0], acc[mi][nj][1]);
            *(float2*)(dst + (size_t)(d + 8) * DH + e) = make_float2(acc[mi][nj][2], acc[mi][nj][3]);
        }
    }
}

// ============================================================================
// small kernels
// ============================================================================
__global__ __launch_bounds__(256) void k_convw(const float* __restrict__ in,
                                               __nv_bfloat16* __restrict__ out) {
    int i = blockIdx.x * 256 + threadIdx.x;
    out[i] = __float2bfloat16(in[i]);
}

// Weff[b,o,h*64+d] = sum_e w_out[o,h*64+e] * ctx_norm[b,h,d,e]
// ctx_norm[d][e] = (sum_s ctxp) * inv_den[d]
__global__ __launch_bounds__(256) void k_weff(const float* __restrict__ ctxp,
                                              const float2* __restrict__ stat,
                                              const float* __restrict__ w_out,
                                              __nv_bfloat16* __restrict__ weff) {
    __shared__ float cs[64][65];
    int bh = blockIdx.x, b = bh >> 2, h = bh & 3;
    int t = threadIdx.x;

    const float* cp = ctxp + ((size_t)bh * NSPL) * (DH * DH);
    #pragma unroll
    for (int i = 0; i < 16; i++) {
        int idx = i * 256 + t, d = idx >> 6, e = idx & 63;
        float v = 0.f;
        #pragma unroll
        for (int sp = 0; sp < NSPL; sp++) v += cp[(size_t)sp * (DH * DH) + idx];
        cs[d][e] = v * stat[b * 256 + h * DH + d].y;
    }
    __syncthreads();

    int o = t;
    float wrow[64];
    const float4* wp = (const float4*)(w_out + (size_t)o * CDIM + h * DH);
    #pragma unroll
    for (int i = 0; i < 16; i++) {
        float4 v = wp[i];
        wrow[i * 4] = v.x; wrow[i * 4 + 1] = v.y; wrow[i * 4 + 2] = v.z; wrow[i * 4 + 3] = v.w;
    }
    __nv_bfloat16* dst = weff + ((size_t)b * CDIM + o) * CDIM + h * DH;
    for (int d = 0; d < DH; d++) {
        float acc = 0.f;
        #pragma unroll 16
        for (int e = 0; e < DH; e++) acc = fmaf(wrow[e], cs[d][e], acc);
        dst[d] = __float2bfloat16(acc);
    }
}

// ============================================================================
// launch
// ============================================================================
extern "C" void kernel_launch(void* const* d_in, const int* in_sizes, int n_in,
                              void* d_out, int out_size)
{
    const float* x     = (const float*)d_in[0];
    const float* w_qkv = (const float*)d_in[1];
    const float* w_out = (const float*)d_in[2];
    const float* b_out = (const float*)d_in[3];
    const float* gamma = (const float*)d_in[4];
    float*       y     = (float*)d_out;

    void *pwb, *pqkv, *pstat, *pctxp, *pweff;
    cudaGetSymbolAddress(&pwb,   g_wb);
    cudaGetSymbolAddress(&pqkv,  g_qkvb);
    cudaGetSymbolAddress(&pstat, g_kstat);
    cudaGetSymbolAddress(&pctxp, g_ctxp);
    cudaGetSymbolAddress(&pweff, g_weff);
    __nv_bfloat16* wb   = (__nv_bfloat16*)pwb;
    __nv_bfloat16* qkvb = (__nv_bfloat16*)pqkv;
    float2*        stat = (float2*)pstat;
    float*         ctxp = (float*)pctxp;
    __nv_bfloat16* weff = (__nv_bfloat16*)pweff;

    // 0) convert weights to bf16
    k_convw<<<(O3 * CDIM) / 256, 256>>>(w_qkv, wb);

    // 1) qkv = w_qkv @ x   (B = x f32, natural layout, fused convert)
    gemm_mma<0, 1><<<dim3(NPIX / 64, O3 / 256, BATCH), 256>>>(
        wb, 0, nullptr, x, (long)CDIM * NPIX,
        nullptr, qkvb, (long)O3 * NPIX, nullptr, nullptr, nullptr);

    // 2) K row stats (softmax folded into ctx + weff)
    k_stat<<<BATCH * 256, 256>>>(qkvb, stat);

    // 3) ctx partials (fused exp) + Weff contraction (applies 1/den)
    ctx_mma<<<dim3(NSPL, HEADS, BATCH), 128>>>(qkvb, stat, ctxp);
    k_weff<<<BATCH * HEADS, 256>>>(ctxp, stat, w_out, weff);

    // 4) y = gamma*(Weff @ q + b_out) + x   (B = q rows of qkv, natural layout)
    gemm_mma<1, 0><<<dim3(NPIX / 64, CDIM / 256, BATCH), 256>>>(
        weff, (long)CDIM * CDIM, qkvb, nullptr, (long)O3 * NPIX,
        y, nullptr, (long)CDIM * NPIX, b_out, gamma, x);
}

// round 12
// speedup vs baseline: 1.0625x; 1.0625x over previous
#include <cuda_runtime.h>
#include <cuda_bf16.h>
#include <cstdint>

#define BATCH 16
#define CDIM  256
#define NPIX  4096
#define O3    768
#define HEADS 4
#define DH    64
#define NSPL  16

// ------------------------- scratch ------------------------------------------
__device__ __nv_bfloat16 g_wb  [O3 * CDIM];                       // w_qkv bf16
__device__ __nv_bfloat16 g_qkvb[(size_t)BATCH * O3 * NPIX];       // qkv  [b][o][n]
__device__ float2        g_kstat[BATCH * 256];                    // {max, 1/sum} per K row
__device__ float         g_ctxp[BATCH * HEADS * NSPL * DH * DH];  // ctx partials (raw exp sums)
__device__ __nv_bfloat16 g_weff[BATCH * CDIM * CDIM];             // Weff [b][o][hd]

// ------------------------- mma helpers --------------------------------------
__device__ __forceinline__ uint32_t cvta_s(const void* p) {
    return (uint32_t)__cvta_generic_to_shared(p);
}
__device__ __forceinline__ void ldsm4(uint32_t* r, uint32_t a) {
    asm volatile("ldmatrix.sync.aligned.m8n8.x4.shared.b16 {%0,%1,%2,%3},[%4];"
                 : "=r"(r[0]), "=r"(r[1]), "=r"(r[2]), "=r"(r[3]) : "r"(a));
}
__device__ __forceinline__ void ldsm4t(uint32_t* r, uint32_t a) {
    asm volatile("ldmatrix.sync.aligned.m8n8.x4.trans.shared.b16 {%0,%1,%2,%3},[%4];"
                 : "=r"(r[0]), "=r"(r[1]), "=r"(r[2]), "=r"(r[3]) : "r"(a));
}
__device__ __forceinline__ void mma16816(float* d, const uint32_t* a, const uint32_t* b) {
    asm volatile(
        "mma.sync.aligned.m16n8k16.row.col.f32.bf16.bf16.f32 "
        "{%0,%1,%2,%3},{%4,%5,%6,%7},{%8,%9},{%0,%1,%2,%3};"
        : "+f"(d[0]), "+f"(d[1]), "+f"(d[2]), "+f"(d[3])
        : "r"(a[0]), "r"(a[1]), "r"(a[2]), "r"(a[3]), "r"(b[0]), "r"(b[1]));
}
__device__ __forceinline__ uint4 cvt8_bf16(float4 lo, float4 hi) {
    __nv_bfloat162 p0 = __floats2bfloat162_rn(lo.x, lo.y);
    __nv_bfloat162 p1 = __floats2bfloat162_rn(lo.z, lo.w);
    __nv_bfloat162 p2 = __floats2bfloat162_rn(hi.x, hi.y);
    __nv_bfloat162 p3 = __floats2bfloat162_rn(hi.z, hi.w);
    uint4 r;
    r.x = *(uint32_t*)&p0; r.y = *(uint32_t*)&p1;
    r.z = *(uint32_t*)&p2; r.w = *(uint32_t*)&p3;
    return r;
}
__device__ __forceinline__ uint32_t exp_bf162(uint32_t wv, float mx) {
    __nv_bfloat162 h = *(__nv_bfloat162*)&wv;
    __nv_bfloat162 r = __floats2bfloat162_rn(__expf(__low2float(h) - mx),
                                             __expf(__high2float(h) - mx));
    return *(uint32_t*)&r;
}
__device__ __forceinline__ uint4 exp_u4(uint4 v, float mx) {
    uint4 r;
    r.x = exp_bf162(v.x, mx); r.y = exp_bf162(v.y, mx);
    r.z = exp_bf162(v.z, mx); r.w = exp_bf162(v.w, mx);
    return r;
}

// ============================================================================
// bf16 HMMA GEMM (R7 proven config):  C[b][M][4096] = A[b][M][256] @ B[b][256][4096]
//   BM=128, BN=128, BK=32.  256 thr = 8 warps (2x4), warp tile 64x32.
//   A: [M][256] bf16 K-major.  B: natural [K][N]; bf16 (BF32=0) or f32 with
//   on-the-fly convert (BF32=1); trans-ldmatrix from XOR-swizzled smem.
//   Double-buffered smem + register prefetch.
// EPI 0: bf16 out.  EPI 1: y = gamma[m]*(acc+bias[m]) + x  (fp32)
// ============================================================================
template <int EPI, int BF32>
__global__ void __launch_bounds__(256, 2)
gemm_mma(const __nv_bfloat16* __restrict__ A, long strideA,
         const __nv_bfloat16* __restrict__ Bb16, const float* __restrict__ Bf32,
         long strideB,
         float* __restrict__ outf, __nv_bfloat16* __restrict__ outb,
         long strideC,
         const float* __restrict__ bias, const float* __restrict__ gamma,
         const float* __restrict__ xres)
{
    __shared__ __nv_bfloat16 As[2][128][40];   // padded rows
    __shared__ __nv_bfloat16 Bs[2][32][128];   // XOR-swizzled (ngrp ^ (k&15))

    const int t = threadIdx.x, lane = t & 31, w = t >> 5;
    const int wm = w >> 2, wn = w & 3;
    const int b = blockIdx.z, m0 = blockIdx.y * 128, n0 = blockIdx.x * 128;

    const __nv_bfloat16* Ab = A + (size_t)b * strideA;
    const __nv_bfloat16* Bb = BF32 ? nullptr : (Bb16 + (size_t)b * strideB);
    const float*         Bf = BF32 ? (Bf32 + (size_t)b * strideB) : nullptr;

    float acc[4][4][4];
    #pragma unroll
    for (int i = 0; i < 4; i++)
        #pragma unroll
        for (int j = 0; j < 4; j++)
            #pragma unroll
            for (int c = 0; c < 4; c++) acc[i][j][c] = 0.f;

    // ---- staging coords ----
    const int am0 = t >> 2, akg = (t & 3) * 8;          // A rows 0..63 / +64
    const int bk0 = t >> 4, bng = t & 15;               // B rows 0..15 / +16
    const int bp0 = (bng ^ (bk0 & 15)) * 8;             // swizzled col (elems)
    const int bp1 = (bng ^ ((bk0 + 16) & 15)) * 8;

    // ---- fragment source addresses ----
    const int a_row = (lane & 7) + 8 * ((lane >> 3) & 1);
    const int a_kad = 8 * (lane >> 4);
    const int b_krow = lane & 15;
    const int b_nsub = lane >> 4;

    uint4 ra0, ra1, rb0, rb1;

    // prefetch tile 0
    ra0 = *(const uint4*)(Ab + (size_t)(m0 + am0) * CDIM + akg);
    ra1 = *(const uint4*)(Ab + (size_t)(m0 + am0 + 64) * CDIM + akg);
    if (BF32) {
        const float* r0 = Bf + (size_t)bk0 * NPIX + n0 + bng * 8;
        const float* r1 = Bf + (size_t)(bk0 + 16) * NPIX + n0 + bng * 8;
        rb0 = cvt8_bf16(*(const float4*)r0, *(const float4*)(r0 + 4));
        rb1 = cvt8_bf16(*(const float4*)r1, *(const float4*)(r1 + 4));
    } else {
        rb0 = *(const uint4*)(Bb + (size_t)bk0 * NPIX + n0 + bng * 8);
        rb1 = *(const uint4*)(Bb + (size_t)(bk0 + 16) * NPIX + n0 + bng * 8);
    }
    *(uint4*)&As[0][am0][akg]      = ra0;
    *(uint4*)&As[0][am0 + 64][akg] = ra1;
    *(uint4*)&Bs[0][bk0][bp0]      = rb0;
    *(uint4*)&Bs[0][bk0 + 16][bp1] = rb1;
    __syncthreads();

    const int KT = CDIM / 32;
    #pragma unroll 1
    for (int it = 0; it < KT; it++) {
        const int cur = it & 1, nxt = cur ^ 1;
        const int kN = (it + 1) * 32;
        if (it + 1 < KT) {
            ra0 = *(const uint4*)(Ab + (size_t)(m0 + am0) * CDIM + kN + akg);
            ra1 = *(const uint4*)(Ab + (size_t)(m0 + am0 + 64) * CDIM + kN + akg);
            if (BF32) {
                const float* r0 = Bf + (size_t)(kN + bk0) * NPIX + n0 + bng * 8;
                const float* r1 = Bf + (size_t)(kN + bk0 + 16) * NPIX + n0 + bng * 8;
                rb0 = cvt8_bf16(*(const float4*)r0, *(const float4*)(r0 + 4));
                rb1 = cvt8_bf16(*(const float4*)r1, *(const float4*)(r1 + 4));
            } else {
                rb0 = *(const uint4*)(Bb + (size_t)(kN + bk0) * NPIX + n0 + bng * 8);
                rb1 = *(const uint4*)(Bb + (size_t)(kN + bk0 + 16) * NPIX + n0 + bng * 8);
            }
        }

        #pragma unroll
        for (int ki = 0; ki < 32; ki += 16) {
            uint32_t af[4][4], bfr[2][4];
            #pragma unroll
            for (int mi = 0; mi < 4; mi++)
                ldsm4(af[mi], cvta_s(&As[cur][wm * 64 + mi * 16 + a_row][ki + a_kad]));
            #pragma unroll
            for (int n2 = 0; n2 < 2; n2++) {
                int krow = ki + b_krow;
                int glog = wn * 4 + n2 * 2 + b_nsub;
                int gphy = glog ^ (krow & 15);
                ldsm4t(bfr[n2], cvta_s(&Bs[cur][krow][gphy * 8]));
            }
            #pragma unroll
            for (int mi = 0; mi < 4; mi++)
                #pragma unroll
                for (int nj = 0; nj < 4; nj++)
                    mma16816(acc[mi][nj], af[mi], &bfr[nj >> 1][(nj & 1) * 2]);
        }

        if (it + 1 < KT) {
            *(uint4*)&As[nxt][am0][akg]      = ra0;
            *(uint4*)&As[nxt][am0 + 64][akg] = ra1;
            *(uint4*)&Bs[nxt][bk0][bp0]      = rb0;
            *(uint4*)&Bs[nxt][bk0 + 16][bp1] = rb1;
        }
        __syncthreads();
    }

    const int gid = lane >> 2, tig = lane & 3;
    #pragma unroll
    for (int mi = 0; mi < 4; mi++) {
        int m = m0 + wm * 64 + mi * 16 + gid;
        if (EPI == 0) {
            __nv_bfloat16* C0 = outb + (size_t)b * strideC + (size_t)m * NPIX;
            __nv_bfloat16* C1 = C0 + 8 * NPIX;
            #pragma unroll
            for (int nj = 0; nj < 4; nj++) {
                int n = n0 + wn * 32 + nj * 8 + tig * 2;
                __nv_bfloat162 lo = __floats2bfloat162_rn(acc[mi][nj][0], acc[mi][nj][1]);
                __nv_bfloat162 hi = __floats2bfloat162_rn(acc[mi][nj][2], acc[mi][nj][3]);
                *(__nv_bfloat162*)(C0 + n) = lo;
                *(__nv_bfloat162*)(C1 + n) = hi;
            }
        } else {
            const float g0 = gamma[m], g1 = gamma[m + 8];
            const float bo0 = bias[m], bo1 = bias[m + 8];
            float*       C0 = outf + (size_t)b * strideC + (size_t)m * NPIX;
            float*       C1 = C0 + 8 * NPIX;
            const float* X0 = xres + (size_t)b * strideC + (size_t)m * NPIX;
            const float* X1 = X0 + 8 * NPIX;
            #pragma unroll
            for (int nj = 0; nj < 4; nj++) {
                int n = n0 + wn * 32 + nj * 8 + tig * 2;
                float2 x0 = *(const float2*)(X0 + n);
                float2 x1 = *(const float2*)(X1 + n);
                float2 o0, o1;
                o0.x = fmaf(g0, acc[mi][nj][0] + bo0, x0.x);
                o0.y = fmaf(g0, acc[mi][nj][1] + bo0, x0.y);
                o1.x = fmaf(g1, acc[mi][nj][2] + bo1, x1.x);
                o1.y = fmaf(g1, acc[mi][nj][3] + bo1, x1.y);
                *(float2*)(C0 + n) = o0;
                *(float2*)(C1 + n) = o1;
            }
        }
    }
}

// ============================================================================
// K row stats: per row (b, hd): mx = max_n k, inv = 1/sum_n exp(k - mx)
// ============================================================================
__global__ __launch_bounds__(256)
void k_stat(const __nv_bfloat16* __restrict__ qkv, float2* __restrict__ stat)
{
    int r = blockIdx.x, b = r >> 8, hd = r & 255;
    const uint4* row4 = (const uint4*)(qkv + ((size_t)b * O3 + 256 + hd) * NPIX);
    int t = threadIdx.x;

    uint4 u0 = row4[t * 2], u1 = row4[t * 2 + 1];
    uint32_t wd[8] = { u0.x, u0.y, u0.z, u0.w, u1.x, u1.y, u1.z, u1.w };
    float f[16];
    #pragma unroll
    for (int i = 0; i < 8; i++) {
        __nv_bfloat162 h = *(__nv_bfloat162*)&wd[i];
        f[2 * i]     = __low2float(h);
        f[2 * i + 1] = __high2float(h);
    }

    float mx = -3.4e38f;
    #pragma unroll
    for (int i = 0; i < 16; i++) mx = fmaxf(mx, f[i]);

    __shared__ float sred[8];
    int lane = t & 31, wr = t >> 5;
    #pragma unroll
    for (int o = 16; o; o >>= 1) mx = fmaxf(mx, __shfl_xor_sync(~0u, mx, o));
    if (lane == 0) sred[wr] = mx;
    __syncthreads();
    if (t < 8) {
        float m2 = sred[t];
        #pragma unroll
        for (int o = 4; o; o >>= 1) m2 = fmaxf(m2, __shfl_xor_sync(0xffu, m2, o));
        if (t == 0) sred[0] = m2;
    }
    __syncthreads();
    mx = sred[0];
    __syncthreads();

    float sum = 0.f;
    #pragma unroll
    for (int i = 0; i < 16; i++) sum += __expf(f[i] - mx);
    #pragma unroll
    for (int o = 16; o; o >>= 1) sum += __shfl_xor_sync(~0u, sum, o);
    if (lane == 0) sred[wr] = sum;
    __syncthreads();
    if (t < 8) {
        float s2 = sred[t];
        #pragma unroll
        for (int o = 4; o; o >>= 1) s2 += __shfl_xor_sync(0xffu, s2, o);
        if (t == 0) stat[r] = make_float2(mx, 1.0f / s2);
    }
}

// ============================================================================
// ctx partial (fused exp): ctxp[b,h,s][d][e] = sum_{n in split} exp(K[d,n]-mx[d]) * V[e,n]
// NSPL=16 (256 n per split), BK=64, double-buffered, 128 thr (4 warps 2x2).
// Staging: 4 uint4 per thread covers the 64x64 tile exactly.
// ============================================================================
__global__ void __launch_bounds__(128)
ctx_mma(const __nv_bfloat16* __restrict__ qkv, const float2* __restrict__ stat,
        float* __restrict__ ctxp)
{
    __shared__ __nv_bfloat16 Ks[2][64][72];
    __shared__ __nv_bfloat16 Vs[2][64][72];

    const int s = blockIdx.x, h = blockIdx.y, b = blockIdx.z;
    const int t = threadIdx.x, lane = t & 31, w = t >> 5;
    const int wm = w >> 1, wn = w & 1;
    const int NPER = NPIX / NSPL;       // 256

    const __nv_bfloat16* kb = qkv + ((size_t)b * O3 + 256 + h * DH) * NPIX + s * NPER;
    const __nv_bfloat16* vb = qkv + ((size_t)b * O3 + 512 + h * DH) * NPIX + s * NPER;

    // staging: i in 0..3, row = (i*128+t)>>3 (0..63), col = (t&7)*8
    const int scol = (t & 7) * 8;
    int   srow[4];
    float mxv[4];
    #pragma unroll
    for (int i = 0; i < 4; i++) {
        srow[i] = (i * 128 + t) >> 3;
        mxv[i]  = stat[b * 256 + h * DH + srow[i]].x;
    }

    float acc[2][4][4];
    #pragma unroll
    for (int i = 0; i < 2; i++)
        #pragma unroll
        for (int j = 0; j < 4; j++)
            #pragma unroll
            for (int c = 0; c < 4; c++) acc[i][j][c] = 0.f;

    const int a_row = (lane & 7) + 8 * ((lane >> 3) & 1);
    const int a_kad = 8 * (lane >> 4);
    const int b_row = (lane & 7) + 8 * ((lane >> 4) & 1);
    const int b_kad = 8 * ((lane >> 3) & 1);

    uint4 rk[4], rv[4];

    // stage 0
    #pragma unroll
    for (int i = 0; i < 4; i++) {
        uint4 kv = *(const uint4*)(kb + (size_t)srow[i] * NPIX + scol);
        *(uint4*)&Ks[0][srow[i]][scol] = exp_u4(kv, mxv[i]);
        *(uint4*)&Vs[0][srow[i]][scol] = *(const uint4*)(vb + (size_t)srow[i] * NPIX + scol);
    }
    __syncthreads();

    const int IT = NPER / 64;           // 4
    #pragma unroll 1
    for (int it = 0; it < IT; it++) {
        const int cur = it & 1, nxt = cur ^ 1;
        const int kN = (it + 1) * 64;
        if (it + 1 < IT) {
            #pragma unroll
            for (int i = 0; i < 4; i++) {
                rk[i] = *(const uint4*)(kb + (size_t)srow[i] * NPIX + kN + scol);
                rv[i] = *(const uint4*)(vb + (size_t)srow[i] * NPIX + kN + scol);
            }
        }

        #pragma unroll
        for (int ki = 0; ki < 64; ki += 16) {
            uint32_t af[2][4], bfr[2][4];
            #pragma unroll
            for (int mi = 0; mi < 2; mi++)
                ldsm4(af[mi], cvta_s(&Ks[cur][wm * 32 + mi * 16 + a_row][ki + a_kad]));
            #pragma unroll
            for (int n2 = 0; n2 < 2; n2++)
                ldsm4(bfr[n2], cvta_s(&Vs[cur][wn * 32 + n2 * 16 + b_row][ki + b_kad]));
            #pragma unroll
            for (int mi = 0; mi < 2; mi++)
                #pragma unroll
                for (int nj = 0; nj < 4; nj++)
                    mma16816(acc[mi][nj], af[mi], &bfr[nj >> 1][(nj & 1) * 2]);
        }

        if (it + 1 < IT) {
            #pragma unroll
            for (int i = 0; i < 4; i++) {
                *(uint4*)&Ks[nxt][srow[i]][scol] = exp_u4(rk[i], mxv[i]);
                *(uint4*)&Vs[nxt][srow[i]][scol] = rv[i];
            }
        }
        __syncthreads();
    }

    const int gid = lane >> 2, tig = lane & 3;
    float* dst = ctxp + (((size_t)(b * HEADS + h) * NSPL + s)) * (DH * DH);
    #pragma unroll
    for (int mi = 0; mi < 2; mi++) {
        int d = wm * 32 + mi * 16 + gid;
        #pragma unroll
        for (int nj = 0; nj < 4; nj++) {
            int e = wn * 32 + nj * 8 + tig * 2;
            *(float2*)(dst + (size_t)d * DH + e)       = make_float2(acc[mi][nj][0], acc[mi][nj][1]);
            *(float2*)(dst + (size_t)(d + 8) * DH + e) = make_float2(acc[mi][nj][2], acc[mi][nj][3]);
        }
    }
}

// ============================================================================
// small kernels
// ============================================================================
__global__ __launch_bounds__(256) void k_convw(const float* __restrict__ in,
                                               __nv_bfloat16* __restrict__ out) {
    int i = blockIdx.x * 256 + threadIdx.x;
    out[i] = __float2bfloat16(in[i]);
}

// Weff[b,o,h*64+d] = sum_e w_out[o,h*64+e] * ctx_norm[b,h,d,e]
// ctx_norm[d][e] = (sum_s ctxp) * inv_den[d]
__global__ __launch_bounds__(256) void k_weff(const float* __restrict__ ctxp,
                                              const float2* __restrict__ stat,
                                              const float* __restrict__ w_out,
                                              __nv_bfloat16* __restrict__ weff) {
    __shared__ float cs[64][65];
    int bh = blockIdx.x, b = bh >> 2, h = bh & 3;
    int t = threadIdx.x;

    const float* cp = ctxp + ((size_t)bh * NSPL) * (DH * DH);
    #pragma unroll
    for (int i = 0; i < 16; i++) {
        int idx = i * 256 + t, d = idx >> 6, e = idx & 63;
        float v = 0.f;
        #pragma unroll
        for (int sp = 0; sp < NSPL; sp++) v += cp[(size_t)sp * (DH * DH) + idx];
        cs[d][e] = v * stat[b * 256 + h * DH + d].y;
    }
    __syncthreads();

    int o = t;
    float wrow[64];
    const float4* wp = (const float4*)(w_out + (size_t)o * CDIM + h * DH);
    #pragma unroll
    for (int i = 0; i < 16; i++) {
        float4 v = wp[i];
        wrow[i * 4] = v.x; wrow[i * 4 + 1] = v.y; wrow[i * 4 + 2] = v.z; wrow[i * 4 + 3] = v.w;
    }
    __nv_bfloat16* dst = weff + ((size_t)b * CDIM + o) * CDIM + h * DH;
    for (int d = 0; d < DH; d++) {
        float acc = 0.f;
        #pragma unroll 16
        for (int e = 0; e < DH; e++) acc = fmaf(wrow[e], cs[d][e], acc);
        dst[d] = __float2bfloat16(acc);
    }
}

// ============================================================================
// launch
// ============================================================================
extern "C" void kernel_launch(void* const* d_in, const int* in_sizes, int n_in,
                              void* d_out, int out_size)
{
    const float* x     = (const float*)d_in[0];
    const float* w_qkv = (const float*)d_in[1];
    const float* w_out = (const float*)d_in[2];
    const float* b_out = (const float*)d_in[3];
    const float* gamma = (const float*)d_in[4];
    float*       y     = (float*)d_out;

    void *pwb, *pqkv, *pstat, *pctxp, *pweff;
    cudaGetSymbolAddress(&pwb,   g_wb);
    cudaGetSymbolAddress(&pqkv,  g_qkvb);
    cudaGetSymbolAddress(&pstat, g_kstat);
    cudaGetSymbolAddress(&pctxp, g_ctxp);
    cudaGetSymbolAddress(&pweff, g_weff);
    __nv_bfloat16* wb   = (__nv_bfloat16*)pwb;
    __nv_bfloat16* qkvb = (__nv_bfloat16*)pqkv;
    float2*        stat = (float2*)pstat;
    float*         ctxp = (float*)pctxp;
    __nv_bfloat16* weff = (__nv_bfloat16*)pweff;

    // 0) convert weights to bf16
    k_convw<<<(O3 * CDIM) / 256, 256>>>(w_qkv, wb);

    // 1) qkv = w_qkv @ x   (B = x f32, natural layout, fused convert) — R7 geometry
    gemm_mma<0, 1><<<dim3(NPIX / 128, O3 / 128, BATCH), 256>>>(
        wb, 0, nullptr, x, (long)CDIM * NPIX,
        nullptr, qkvb, (long)O3 * NPIX, nullptr, nullptr, nullptr);

    // 2) K row stats (softmax folded into ctx + weff)
    k_stat<<<BATCH * 256, 256>>>(qkvb, stat);

    // 3) ctx partials (fused exp) + Weff contraction (applies 1/den)
    ctx_mma<<<dim3(NSPL, HEADS, BATCH), 128>>>(qkvb, stat, ctxp);
    k_weff<<<BATCH * HEADS, 256>>>(ctxp, stat, w_out, weff);

    // 4) y = gamma*(Weff @ q + b_out) + x   — R7 geometry
    gemm_mma<1, 0><<<dim3(NPIX / 128, CDIM / 128, BATCH), 256>>>(
        weff, (long)CDIM * CDIM, qkvb, nullptr, (long)O3 * NPIX,
        y, nullptr, (long)CDIM * NPIX, b_out, gamma, x);
}

// round 14
// speedup vs baseline: 1.0781x; 1.0147x over previous
#include <cuda_runtime.h>
#include <cuda_bf16.h>
#include <cstdint>

#define BATCH 16
#define CDIM  256
#define NPIX  4096
#define O3    768
#define HEADS 4
#define DH    64
#define NSPL  16

// ------------------------- scratch ------------------------------------------
__device__ __nv_bfloat16 g_wb  [O3 * CDIM];                       // w_qkv bf16
__device__ __nv_bfloat16 g_qkvb[(size_t)BATCH * O3 * NPIX];       // qkv  [b][o][n]
__device__ float2        g_kstat[BATCH * 256];                    // {max, 1/sum} per K row
__device__ float         g_ctxp[BATCH * HEADS * NSPL * DH * DH];  // ctx partials (raw exp sums)
__device__ __nv_bfloat16 g_weff[BATCH * CDIM * CDIM];             // Weff [b][o][hd]

// ------------------------- helpers ------------------------------------------
__device__ __forceinline__ uint32_t cvta_s(const void* p) {
    return (uint32_t)__cvta_generic_to_shared(p);
}
__device__ __forceinline__ void cp16(uint32_t smem, const void* g) {
    asm volatile("cp.async.cg.shared.global [%0], [%1], 16;" :: "r"(smem), "l"(g));
}
#define CP_COMMIT() asm volatile("cp.async.commit_group;" ::: "memory")
#define CP_WAIT0()  asm volatile("cp.async.wait_group 0;" ::: "memory")

__device__ __forceinline__ void ldsm4(uint32_t* r, uint32_t a) {
    asm volatile("ldmatrix.sync.aligned.m8n8.x4.shared.b16 {%0,%1,%2,%3},[%4];"
                 : "=r"(r[0]), "=r"(r[1]), "=r"(r[2]), "=r"(r[3]) : "r"(a));
}
__device__ __forceinline__ void ldsm4t(uint32_t* r, uint32_t a) {
    asm volatile("ldmatrix.sync.aligned.m8n8.x4.trans.shared.b16 {%0,%1,%2,%3},[%4];"
                 : "=r"(r[0]), "=r"(r[1]), "=r"(r[2]), "=r"(r[3]) : "r"(a));
}
__device__ __forceinline__ void mma16816(float* d, const uint32_t* a, const uint32_t* b) {
    asm volatile(
        "mma.sync.aligned.m16n8k16.row.col.f32.bf16.bf16.f32 "
        "{%0,%1,%2,%3},{%4,%5,%6,%7},{%8,%9},{%0,%1,%2,%3};"
        : "+f"(d[0]), "+f"(d[1]), "+f"(d[2]), "+f"(d[3])
        : "r"(a[0]), "r"(a[1]), "r"(a[2]), "r"(a[3]), "r"(b[0]), "r"(b[1]));
}
__device__ __forceinline__ uint4 cvt8_bf16(float4 lo, float4 hi) {
    __nv_bfloat162 p0 = __floats2bfloat162_rn(lo.x, lo.y);
    __nv_bfloat162 p1 = __floats2bfloat162_rn(lo.z, lo.w);
    __nv_bfloat162 p2 = __floats2bfloat162_rn(hi.x, hi.y);
    __nv_bfloat162 p3 = __floats2bfloat162_rn(hi.z, hi.w);
    uint4 r;
    r.x = *(uint32_t*)&p0; r.y = *(uint32_t*)&p1;
    r.z = *(uint32_t*)&p2; r.w = *(uint32_t*)&p3;
    return r;
}
__device__ __forceinline__ uint32_t exp_bf162(uint32_t wv, float mx) {
    __nv_bfloat162 h = *(__nv_bfloat162*)&wv;
    __nv_bfloat162 r = __floats2bfloat162_rn(__expf(__low2float(h) - mx),
                                             __expf(__high2float(h) - mx));
    return *(uint32_t*)&r;
}
__device__ __forceinline__ uint4 exp_u4(uint4 v, float mx) {
    uint4 r;
    r.x = exp_bf162(v.x, mx); r.y = exp_bf162(v.y, mx);
    r.z = exp_bf162(v.z, mx); r.w = exp_bf162(v.w, mx);
    return r;
}

// ============================================================================
// bf16 HMMA GEMM (R7 geometry + cp.async staging):
//   C[b][M][4096] = A[b][M][256] @ B[b][256][4096]
//   BM=128, BN=128, BK=32.  256 thr = 8 warps (2x4), warp tile 64x32.
//   A: bf16 K-major via cp.async.  B: natural [K][N]; bf16 via cp.async
//   (BF32=0) or f32 via register-convert (BF32=1). Double-buffered.
// EPI 0: bf16 out.  EPI 1: y = gamma[m]*(acc+bias[m]) + x  (fp32)
// ============================================================================
template <int EPI, int BF32>
__global__ void __launch_bounds__(256, 2)
gemm_mma(const __nv_bfloat16* __restrict__ A, long strideA,
         const __nv_bfloat16* __restrict__ Bb16, const float* __restrict__ Bf32,
         long strideB,
         float* __restrict__ outf, __nv_bfloat16* __restrict__ outb,
         long strideC,
         const float* __restrict__ bias, const float* __restrict__ gamma,
         const float* __restrict__ xres)
{
    __shared__ __nv_bfloat16 As[2][128][40];   // 80B rows (16B-multiple stride)
    __shared__ __nv_bfloat16 Bs[2][32][128];   // XOR-swizzled (ngrp ^ (k&15))

    const int t = threadIdx.x, lane = t & 31, w = t >> 5;
    const int wm = w >> 2, wn = w & 3;
    const int b = blockIdx.z, m0 = blockIdx.y * 128, n0 = blockIdx.x * 128;

    const __nv_bfloat16* Ab = A + (size_t)b * strideA;
    const __nv_bfloat16* Bb = BF32 ? nullptr : (Bb16 + (size_t)b * strideB);
    const float*         Bf = BF32 ? (Bf32 + (size_t)b * strideB) : nullptr;

    float acc[4][4][4];
    #pragma unroll
    for (int i = 0; i < 4; i++)
        #pragma unroll
        for (int j = 0; j < 4; j++)
            #pragma unroll
            for (int c = 0; c < 4; c++) acc[i][j][c] = 0.f;

    // ---- staging coords ----
    const int am0 = t >> 2, akg = (t & 3) * 8;          // A rows 0..63 / +64
    const int bk0 = t >> 4, bng = t & 15;               // B rows 0..15 / +16
    const int bp0 = (bng ^ (bk0 & 15)) * 8;             // swizzled col (elems)
    const int bp1 = (bng ^ ((bk0 + 16) & 15)) * 8;

    // ---- fragment source addresses ----
    const int a_row = (lane & 7) + 8 * ((lane >> 3) & 1);
    const int a_kad = 8 * (lane >> 4);
    const int b_krow = lane & 15;
    const int b_nsub = lane >> 4;

    uint4 rb0, rb1;

    // ---- stage 0 ----
    cp16(cvta_s(&As[0][am0][akg]),      Ab + (size_t)(m0 + am0) * CDIM + akg);
    cp16(cvta_s(&As[0][am0 + 64][akg]), Ab + (size_t)(m0 + am0 + 64) * CDIM + akg);
    if (BF32) {
        const float* r0 = Bf + (size_t)bk0 * NPIX + n0 + bng * 8;
        const float* r1 = Bf + (size_t)(bk0 + 16) * NPIX + n0 + bng * 8;
        rb0 = cvt8_bf16(*(const float4*)r0, *(const float4*)(r0 + 4));
        rb1 = cvt8_bf16(*(const float4*)r1, *(const float4*)(r1 + 4));
        *(uint4*)&Bs[0][bk0][bp0]      = rb0;
        *(uint4*)&Bs[0][bk0 + 16][bp1] = rb1;
    } else {
        cp16(cvta_s(&Bs[0][bk0][bp0]),      Bb + (size_t)bk0 * NPIX + n0 + bng * 8);
        cp16(cvta_s(&Bs[0][bk0 + 16][bp1]), Bb + (size_t)(bk0 + 16) * NPIX + n0 + bng * 8);
    }
    CP_COMMIT();
    CP_WAIT0();
    __syncthreads();

    const int KT = CDIM / 32;
    #pragma unroll 1
    for (int it = 0; it < KT; it++) {
        const int cur = it & 1, nxt = cur ^ 1;
        const int kN = (it + 1) * 32;
        if (it + 1 < KT) {
            cp16(cvta_s(&As[nxt][am0][akg]),      Ab + (size_t)(m0 + am0) * CDIM + kN + akg);
            cp16(cvta_s(&As[nxt][am0 + 64][akg]), Ab + (size_t)(m0 + am0 + 64) * CDIM + kN + akg);
            if (BF32) {
                const float* r0 = Bf + (size_t)(kN + bk0) * NPIX + n0 + bng * 8;
                const float* r1 = Bf + (size_t)(kN + bk0 + 16) * NPIX + n0 + bng * 8;
                rb0 = cvt8_bf16(*(const float4*)r0, *(const float4*)(r0 + 4));
                rb1 = cvt8_bf16(*(const float4*)r1, *(const float4*)(r1 + 4));
            } else {
                cp16(cvta_s(&Bs[nxt][bk0][bp0]),      Bb + (size_t)(kN + bk0) * NPIX + n0 + bng * 8);
                cp16(cvta_s(&Bs[nxt][bk0 + 16][bp1]), Bb + (size_t)(kN + bk0 + 16) * NPIX + n0 + bng * 8);
            }
            CP_COMMIT();
        }

        #pragma unroll
        for (int ki = 0; ki < 32; ki += 16) {
            uint32_t af[4][4], bfr[2][4];
            #pragma unroll
            for (int mi = 0; mi < 4; mi++)
                ldsm4(af[mi], cvta_s(&As[cur][wm * 64 + mi * 16 + a_row][ki + a_kad]));
            #pragma unroll
            for (int n2 = 0; n2 < 2; n2++) {
                int krow = ki + b_krow;
                int glog = wn * 4 + n2 * 2 + b_nsub;
                int gphy = glog ^ (krow & 15);
                ldsm4t(bfr[n2], cvta_s(&Bs[cur][krow][gphy * 8]));
            }
            #pragma unroll
            for (int mi = 0; mi < 4; mi++)
                #pragma unroll
                for (int nj = 0; nj < 4; nj++)
                    mma16816(acc[mi][nj], af[mi], &bfr[nj >> 1][(nj & 1) * 2]);
        }

        if (it + 1 < KT) {
            if (BF32) {
                *(uint4*)&Bs[nxt][bk0][bp0]      = rb0;
                *(uint4*)&Bs[nxt][bk0 + 16][bp1] = rb1;
            }
            CP_WAIT0();
        }
        __syncthreads();
    }

    const int gid = lane >> 2, tig = lane & 3;
    #pragma unroll
    for (int mi = 0; mi < 4; mi++) {
        int m = m0 + wm * 64 + mi * 16 + gid;
        if (EPI == 0) {
            __nv_bfloat16* C0 = outb + (size_t)b * strideC + (size_t)m * NPIX;
            __nv_bfloat16* C1 = C0 + 8 * NPIX;
            #pragma unroll
            for (int nj = 0; nj < 4; nj++) {
                int n = n0 + wn * 32 + nj * 8 + tig * 2;
                __nv_bfloat162 lo = __floats2bfloat162_rn(acc[mi][nj][0], acc[mi][nj][1]);
                __nv_bfloat162 hi = __floats2bfloat162_rn(acc[mi][nj][2], acc[mi][nj][3]);
                *(__nv_bfloat162*)(C0 + n) = lo;
                *(__nv_bfloat162*)(C1 + n) = hi;
            }
        } else {
            const float g0 = gamma[m], g1 = gamma[m + 8];
            const float bo0 = bias[m], bo1 = bias[m + 8];
            float*       C0 = outf + (size_t)b * strideC + (size_t)m * NPIX;
            float*       C1 = C0 + 8 * NPIX;
            const float* X0 = xres + (size_t)b * strideC + (size_t)m * NPIX;
            const float* X1 = X0 + 8 * NPIX;
            #pragma unroll
            for (int nj = 0; nj < 4; nj++) {
                int n = n0 + wn * 32 + nj * 8 + tig * 2;
                float2 x0 = *(const float2*)(X0 + n);
                float2 x1 = *(const float2*)(X1 + n);
                float2 o0, o1;
                o0.x = fmaf(g0, acc[mi][nj][0] + bo0, x0.x);
                o0.y = fmaf(g0, acc[mi][nj][1] + bo0, x0.y);
                o1.x = fmaf(g1, acc[mi][nj][2] + bo1, x1.x);
                o1.y = fmaf(g1, acc[mi][nj][3] + bo1, x1.y);
                *(float2*)(C0 + n) = o0;
                *(float2*)(C1 + n) = o1;
            }
        }
    }
}

// ============================================================================
// K row stats: per row (b, hd): mx = max_n k, inv = 1/sum_n exp(k - mx)
// ============================================================================
__global__ __launch_bounds__(256)
void k_stat(const __nv_bfloat16* __restrict__ qkv, float2* __restrict__ stat)
{
    int r = blockIdx.x, b = r >> 8, hd = r & 255;
    const uint4* row4 = (const uint4*)(qkv + ((size_t)b * O3 + 256 + hd) * NPIX);
    int t = threadIdx.x;

    uint4 u0 = row4[t * 2], u1 = row4[t * 2 + 1];
    uint32_t wd[8] = { u0.x, u0.y, u0.z, u0.w, u1.x, u1.y, u1.z, u1.w };
    float f[16];
    #pragma unroll
    for (int i = 0; i < 8; i++) {
        __nv_bfloat162 h = *(__nv_bfloat162*)&wd[i];
        f[2 * i]     = __low2float(h);
        f[2 * i + 1] = __high2float(h);
    }

    float mx = -3.4e38f;
    #pragma unroll
    for (int i = 0; i < 16; i++) mx = fmaxf(mx, f[i]);

    __shared__ float sred[8];
    int lane = t & 31, wr = t >> 5;
    #pragma unroll
    for (int o = 16; o; o >>= 1) mx = fmaxf(mx, __shfl_xor_sync(~0u, mx, o));
    if (lane == 0) sred[wr] = mx;
    __syncthreads();
    if (t < 8) {
        float m2 = sred[t];
        #pragma unroll
        for (int o = 4; o; o >>= 1) m2 = fmaxf(m2, __shfl_xor_sync(0xffu, m2, o));
        if (t == 0) sred[0] = m2;
    }
    __syncthreads();
    mx = sred[0];
    __syncthreads();

    float sum = 0.f;
    #pragma unroll
    for (int i = 0; i < 16; i++) sum += __expf(f[i] - mx);
    #pragma unroll
    for (int o = 16; o; o >>= 1) sum += __shfl_xor_sync(~0u, sum, o);
    if (lane == 0) sred[wr] = sum;
    __syncthreads();
    if (t < 8) {
        float s2 = sred[t];
        #pragma unroll
        for (int o = 4; o; o >>= 1) s2 += __shfl_xor_sync(0xffu, s2, o);
        if (t == 0) stat[r] = make_float2(mx, 1.0f / s2);
    }
}

// ============================================================================
// ctx partial (fused exp): ctxp[b,h,s][d][e] = sum_{n in split} exp(K[d,n]-mx[d]) * V[e,n]
// NSPL=16, BK=64, double-buffered; V staged via cp.async, K via register+exp.
// ============================================================================
__global__ void __launch_bounds__(128)
ctx_mma(const __nv_bfloat16* __restrict__ qkv, const float2* __restrict__ stat,
        float* __restrict__ ctxp)
{
    __shared__ __nv_bfloat16 Ks[2][64][72];
    __shared__ __nv_bfloat16 Vs[2][64][72];

    const int s = blockIdx.x, h = blockIdx.y, b = blockIdx.z;
    const int t = threadIdx.x, lane = t & 31, w = t >> 5;
    const int wm = w >> 1, wn = w & 1;
    const int NPER = NPIX / NSPL;       // 256

    const __nv_bfloat16* kb = qkv + ((size_t)b * O3 + 256 + h * DH) * NPIX + s * NPER;
    const __nv_bfloat16* vb = qkv + ((size_t)b * O3 + 512 + h * DH) * NPIX + s * NPER;

    const int scol = (t & 7) * 8;
    int   srow[4];
    float mxv[4];
    #pragma unroll
    for (int i = 0; i < 4; i++) {
        srow[i] = (i * 128 + t) >> 3;
        mxv[i]  = stat[b * 256 + h * DH + srow[i]].x;
    }

    float acc[2][4][4];
    #pragma unroll
    for (int i = 0; i < 2; i++)
        #pragma unroll
        for (int j = 0; j < 4; j++)
            #pragma unroll
            for (int c = 0; c < 4; c++) acc[i][j][c] = 0.f;

    const int a_row = (lane & 7) + 8 * ((lane >> 3) & 1);
    const int a_kad = 8 * (lane >> 4);
    const int b_row = (lane & 7) + 8 * ((lane >> 4) & 1);
    const int b_kad = 8 * ((lane >> 3) & 1);

    uint4 rk[4];

    // stage 0
    #pragma unroll
    for (int i = 0; i < 4; i++) {
        uint4 kv = *(const uint4*)(kb + (size_t)srow[i] * NPIX + scol);
        *(uint4*)&Ks[0][srow[i]][scol] = exp_u4(kv, mxv[i]);
        cp16(cvta_s(&Vs[0][srow[i]][scol]), vb + (size_t)srow[i] * NPIX + scol);
    }
    CP_COMMIT();
    CP_WAIT0();
    __syncthreads();

    const int IT = NPER / 64;           // 4
    #pragma unroll 1
    for (int it = 0; it < IT; it++) {
        const int cur = it & 1, nxt = cur ^ 1;
        const int kN = (it + 1) * 64;
        if (it + 1 < IT) {
            #pragma unroll
            for (int i = 0; i < 4; i++) {
                cp16(cvta_s(&Vs[nxt][srow[i]][scol]), vb + (size_t)srow[i] * NPIX + kN + scol);
                rk[i] = *(const uint4*)(kb + (size_t)srow[i] * NPIX + kN + scol);
            }
            CP_COMMIT();
        }

        #pragma unroll
        for (int ki = 0; ki < 64; ki += 16) {
            uint32_t af[2][4], bfr[2][4];
            #pragma unroll
            for (int mi = 0; mi < 2; mi++)
                ldsm4(af[mi], cvta_s(&Ks[cur][wm * 32 + mi * 16 + a_row][ki + a_kad]));
            #pragma unroll
            for (int n2 = 0; n2 < 2; n2++)
                ldsm4(bfr[n2], cvta_s(&Vs[cur][wn * 32 + n2 * 16 + b_row][ki + b_kad]));
            #pragma unroll
            for (int mi = 0; mi < 2; mi++)
                #pragma unroll
                for (int nj = 0; nj < 4; nj++)
                    mma16816(acc[mi][nj], af[mi], &bfr[nj >> 1][(nj & 1) * 2]);
        }

        if (it + 1 < IT) {
            #pragma unroll
            for (int i = 0; i < 4; i++)
                *(uint4*)&Ks[nxt][srow[i]][scol] = exp_u4(rk[i], mxv[i]);
            CP_WAIT0();
        }
        __syncthreads();
    }

    const int gid = lane >> 2, tig = lane & 3;
    float* dst = ctxp + (((size_t)(b * HEADS + h) * NSPL + s)) * (DH * DH);
    #pragma unroll
    for (int mi = 0; mi < 2; mi++) {
        int d = wm * 32 + mi * 16 + gid;
        #pragma unroll
        for (int nj = 0; nj < 4; nj++) {
            int e = wn * 32 + nj * 8 + tig * 2;
            *(float2*)(dst + (size_t)d * DH + e)       = make_float2(acc[mi][nj][0], acc[mi][nj][1]);
            *(float2*)(dst + (size_t)(d + 8) * DH + e) = make_float2(acc[mi][nj][2], acc[mi][nj][3]);
        }
    }
}

// ============================================================================
// small kernels
// ============================================================================
__global__ __launch_bounds__(256) void k_convw(const float* __restrict__ in,
                                               __nv_bfloat16* __restrict__ out) {
    int i = blockIdx.x * 256 + threadIdx.x;
    out[i] = __float2bfloat16(in[i]);
}

// Weff[b,o,h*64+d] = sum_e w_out[o,h*64+e] * ctx_norm[b,h,d,e]
__global__ __launch_bounds__(256) void k_weff(const float* __restrict__ ctxp,
                                              const float2* __restrict__ stat,
                                              const float* __restrict__ w_out,
                                              __nv_bfloat16* __restrict__ weff) {
    __shared__ float cs[64][65];
    int bh = blockIdx.x, b = bh >> 2, h = bh & 3;
    int t = threadIdx.x;

    const float* cp = ctxp + ((size_t)bh * NSPL) * (DH * DH);
    #pragma unroll
    for (int i = 0; i < 16; i++) {
        int idx = i * 256 + t, d = idx >> 6, e = idx & 63;
        float v = 0.f;
        #pragma unroll
        for (int sp = 0; sp < NSPL; sp++) v += cp[(size_t)sp * (DH * DH) + idx];
        cs[d][e] = v * stat[b * 256 + h * DH + d].y;
    }
    __syncthreads();

    int o = t;
    float wrow[64];
    const float4* wp = (const float4*)(w_out + (size_t)o * CDIM + h * DH);
    #pragma unroll
    for (int i = 0; i < 16; i++) {
        float4 v = wp[i];
        wrow[i * 4] = v.x; wrow[i * 4 + 1] = v.y; wrow[i * 4 + 2] = v.z; wrow[i * 4 + 3] = v.w;
    }
    __nv_bfloat16* dst = weff + ((size_t)b * CDIM + o) * CDIM + h * DH;
    for (int d = 0; d < DH; d++) {
        float acc = 0.f;
        #pragma unroll 16
        for (int e = 0; e < DH; e++) acc = fmaf(wrow[e], cs[d][e], acc);
        dst[d] = __float2bfloat16(acc);
    }
}

// ============================================================================
// launch
// ============================================================================
extern "C" void kernel_launch(void* const* d_in, const int* in_sizes, int n_in,
                              void* d_out, int out_size)
{
    const float* x     = (const float*)d_in[0];
    const float* w_qkv = (const float*)d_in[1];
    const float* w_out = (const float*)d_in[2];
    const float* b_out = (const float*)d_in[3];
    const float* gamma = (const float*)d_in[4];
    float*       y     = (float*)d_out;

    void *pwb, *pqkv, *pstat, *pctxp, *pweff;
    cudaGetSymbolAddress(&pwb,   g_wb);
    cudaGetSymbolAddress(&pqkv,  g_qkvb);
    cudaGetSymbolAddress(&pstat, g_kstat);
    cudaGetSymbolAddress(&pctxp, g_ctxp);
    cudaGetSymbolAddress(&pweff, g_weff);
    __nv_bfloat16* wb   = (__nv_bfloat16*)pwb;
    __nv_bfloat16* qkvb = (__nv_bfloat16*)pqkv;
    float2*        stat = (float2*)pstat;
    float*         ctxp = (float*)pctxp;
    __nv_bfloat16* weff = (__nv_bfloat16*)pweff;

    // 0) convert weights to bf16
    k_convw<<<(O3 * CDIM) / 256, 256>>>(w_qkv, wb);

    // 1) qkv = w_qkv @ x   (A via cp.async, B = x f32 register-convert)
    gemm_mma<0, 1><<<dim3(NPIX / 128, O3 / 128, BATCH), 256>>>(
        wb, 0, nullptr, x, (long)CDIM * NPIX,
        nullptr, qkvb, (long)O3 * NPIX, nullptr, nullptr, nullptr);

    // 2) K row stats (softmax folded into ctx + weff)
    k_stat<<<BATCH * 256, 256>>>(qkvb, stat);

    // 3) ctx partials (fused exp, V via cp.async) + Weff contraction
    ctx_mma<<<dim3(NSPL, HEADS, BATCH), 128>>>(qkvb, stat, ctxp);
    k_weff<<<BATCH * HEADS, 256>>>(ctxp, stat, w_out, weff);

    // 4) y = gamma*(Weff @ q + b_out) + x   (fully cp.async staging)
    gemm_mma<1, 0><<<dim3(NPIX / 128, CDIM / 128, BATCH), 256>>>(
        weff, (long)CDIM * CDIM, qkvb, nullptr, (long)O3 * NPIX,
        y, nullptr, (long)CDIM * NPIX, b_out, gamma, x);
}

// round 15
// speedup vs baseline: 1.0840x; 1.0055x over previous
#include <cuda_runtime.h>
#include <cuda_bf16.h>
#include <cstdint>

#define BATCH 16
#define CDIM  256
#define NPIX  4096
#define O3    768
#define HEADS 4
#define DH    64
#define NSPL  16
#define NTIL  32            // n-tiles in GEMM1 (NPIX/128)

// ------------------------- scratch ------------------------------------------
__device__ __nv_bfloat16 g_wb  [O3 * CDIM];                       // w_qkv bf16
__device__ __nv_bfloat16 g_qkvb[(size_t)BATCH * O3 * NPIX];       // qkv  [b][o][n]
__device__ float         g_denp[NTIL][BATCH * 256];               // per-n-tile exp sums
__device__ float         g_dinv[BATCH * 256];                     // 1/sum_exp per K row
__device__ float         g_ctxp[BATCH * HEADS * NSPL * DH * DH];  // ctx partials
__device__ __nv_bfloat16 g_weff[BATCH * CDIM * CDIM];             // Weff [b][o][hd]

// ------------------------- helpers ------------------------------------------
__device__ __forceinline__ uint32_t cvta_s(const void* p) {
    return (uint32_t)__cvta_generic_to_shared(p);
}
__device__ __forceinline__ void cp16(uint32_t smem, const void* g) {
    asm volatile("cp.async.cg.shared.global [%0], [%1], 16;" :: "r"(smem), "l"(g));
}
#define CP_COMMIT() asm volatile("cp.async.commit_group;" ::: "memory")
#define CP_WAIT0()  asm volatile("cp.async.wait_group 0;" ::: "memory")

__device__ __forceinline__ void ldsm4(uint32_t* r, uint32_t a) {
    asm volatile("ldmatrix.sync.aligned.m8n8.x4.shared.b16 {%0,%1,%2,%3},[%4];"
                 : "=r"(r[0]), "=r"(r[1]), "=r"(r[2]), "=r"(r[3]) : "r"(a));
}
__device__ __forceinline__ void ldsm4t(uint32_t* r, uint32_t a) {
    asm volatile("ldmatrix.sync.aligned.m8n8.x4.trans.shared.b16 {%0,%1,%2,%3},[%4];"
                 : "=r"(r[0]), "=r"(r[1]), "=r"(r[2]), "=r"(r[3]) : "r"(a));
}
__device__ __forceinline__ void mma16816(float* d, const uint32_t* a, const uint32_t* b) {
    asm volatile(
        "mma.sync.aligned.m16n8k16.row.col.f32.bf16.bf16.f32 "
        "{%0,%1,%2,%3},{%4,%5,%6,%7},{%8,%9},{%0,%1,%2,%3};"
        : "+f"(d[0]), "+f"(d[1]), "+f"(d[2]), "+f"(d[3])
        : "r"(a[0]), "r"(a[1]), "r"(a[2]), "r"(a[3]), "r"(b[0]), "r"(b[1]));
}
__device__ __forceinline__ uint4 cvt8_bf16(float4 lo, float4 hi) {
    __nv_bfloat162 p0 = __floats2bfloat162_rn(lo.x, lo.y);
    __nv_bfloat162 p1 = __floats2bfloat162_rn(lo.z, lo.w);
    __nv_bfloat162 p2 = __floats2bfloat162_rn(hi.x, hi.y);
    __nv_bfloat162 p3 = __floats2bfloat162_rn(hi.z, hi.w);
    uint4 r;
    r.x = *(uint32_t*)&p0; r.y = *(uint32_t*)&p1;
    r.z = *(uint32_t*)&p2; r.w = *(uint32_t*)&p3;
    return r;
}
// exp(k) without max-shift: k = W_qkv.x with unit-variance operands, |k| << 88.
__device__ __forceinline__ uint32_t exp_bf162(uint32_t wv) {
    __nv_bfloat162 h = *(__nv_bfloat162*)&wv;
    __nv_bfloat162 r = __floats2bfloat162_rn(__expf(__low2float(h)),
                                             __expf(__high2float(h)));
    return *(uint32_t*)&r;
}
__device__ __forceinline__ uint4 exp_u4(uint4 v) {
    uint4 r;
    r.x = exp_bf162(v.x); r.y = exp_bf162(v.y);
    r.z = exp_bf162(v.z); r.w = exp_bf162(v.w);
    return r;
}

// ============================================================================
// bf16 HMMA GEMM:  C[b][M][4096] = A[b][M][256] @ B[b][256][4096]
//   BM=128, BN=128, BK=32.  256 thr = 8 warps (2x4), warp tile 64x32.
//   cp.async staging (A always; B when bf16), double-buffered.
//   KSTAT=1: for K-row tiles (m0 in [256,512)), also emit per-n-tile
//   exp-row-sum partials to denp (deterministic fixed slots).
// EPI 0: bf16 out.  EPI 1: y = gamma[m]*(acc+bias[m]) + x  (fp32)
// ============================================================================
template <int EPI, int BF32, int KSTAT>
__global__ void __launch_bounds__(256, 2)
gemm_mma(const __nv_bfloat16* __restrict__ A, long strideA,
         const __nv_bfloat16* __restrict__ Bb16, const float* __restrict__ Bf32,
         long strideB,
         float* __restrict__ outf, __nv_bfloat16* __restrict__ outb,
         long strideC,
         const float* __restrict__ bias, const float* __restrict__ gamma,
         const float* __restrict__ xres, float* __restrict__ denp)
{
    __shared__ __nv_bfloat16 As[2][128][40];
    __shared__ __nv_bfloat16 Bs[2][32][128];

    const int t = threadIdx.x, lane = t & 31, w = t >> 5;
    const int wm = w >> 2, wn = w & 3;
    const int b = blockIdx.z, m0 = blockIdx.y * 128, n0 = blockIdx.x * 128;

    const __nv_bfloat16* Ab = A + (size_t)b * strideA;
    const __nv_bfloat16* Bb = BF32 ? nullptr : (Bb16 + (size_t)b * strideB);
    const float*         Bf = BF32 ? (Bf32 + (size_t)b * strideB) : nullptr;

    float acc[4][4][4];
    #pragma unroll
    for (int i = 0; i < 4; i++)
        #pragma unroll
        for (int j = 0; j < 4; j++)
            #pragma unroll
            for (int c = 0; c < 4; c++) acc[i][j][c] = 0.f;

    const int am0 = t >> 2, akg = (t & 3) * 8;
    const int bk0 = t >> 4, bng = t & 15;
    const int bp0 = (bng ^ (bk0 & 15)) * 8;
    const int bp1 = (bng ^ ((bk0 + 16) & 15)) * 8;

    const int a_row = (lane & 7) + 8 * ((lane >> 3) & 1);
    const int a_kad = 8 * (lane >> 4);
    const int b_krow = lane & 15;
    const int b_nsub = lane >> 4;

    uint4 rb0, rb1;

    cp16(cvta_s(&As[0][am0][akg]),      Ab + (size_t)(m0 + am0) * CDIM + akg);
    cp16(cvta_s(&As[0][am0 + 64][akg]), Ab + (size_t)(m0 + am0 + 64) * CDIM + akg);
    if (BF32) {
        const float* r0 = Bf + (size_t)bk0 * NPIX + n0 + bng * 8;
        const float* r1 = Bf + (size_t)(bk0 + 16) * NPIX + n0 + bng * 8;
        rb0 = cvt8_bf16(*(const float4*)r0, *(const float4*)(r0 + 4));
        rb1 = cvt8_bf16(*(const float4*)r1, *(const float4*)(r1 + 4));
        *(uint4*)&Bs[0][bk0][bp0]      = rb0;
        *(uint4*)&Bs[0][bk0 + 16][bp1] = rb1;
    } else {
        cp16(cvta_s(&Bs[0][bk0][bp0]),      Bb + (size_t)bk0 * NPIX + n0 + bng * 8);
        cp16(cvta_s(&Bs[0][bk0 + 16][bp1]), Bb + (size_t)(bk0 + 16) * NPIX + n0 + bng * 8);
    }
    CP_COMMIT();
    CP_WAIT0();
    __syncthreads();

    const int KT = CDIM / 32;
    #pragma unroll 1
    for (int it = 0; it < KT; it++) {
        const int cur = it & 1, nxt = cur ^ 1;
        const int kN = (it + 1) * 32;
        if (it + 1 < KT) {
            cp16(cvta_s(&As[nxt][am0][akg]),      Ab + (size_t)(m0 + am0) * CDIM + kN + akg);
            cp16(cvta_s(&As[nxt][am0 + 64][akg]), Ab + (size_t)(m0 + am0 + 64) * CDIM + kN + akg);
            if (BF32) {
                const float* r0 = Bf + (size_t)(kN + bk0) * NPIX + n0 + bng * 8;
                const float* r1 = Bf + (size_t)(kN + bk0 + 16) * NPIX + n0 + bng * 8;
                rb0 = cvt8_bf16(*(const float4*)r0, *(const float4*)(r0 + 4));
                rb1 = cvt8_bf16(*(const float4*)r1, *(const float4*)(r1 + 4));
            } else {
                cp16(cvta_s(&Bs[nxt][bk0][bp0]),      Bb + (size_t)(kN + bk0) * NPIX + n0 + bng * 8);
                cp16(cvta_s(&Bs[nxt][bk0 + 16][bp1]), Bb + (size_t)(kN + bk0 + 16) * NPIX + n0 + bng * 8);
            }
            CP_COMMIT();
        }

        #pragma unroll
        for (int ki = 0; ki < 32; ki += 16) {
            uint32_t af[4][4], bfr[2][4];
            #pragma unroll
            for (int mi = 0; mi < 4; mi++)
                ldsm4(af[mi], cvta_s(&As[cur][wm * 64 + mi * 16 + a_row][ki + a_kad]));
            #pragma unroll
            for (int n2 = 0; n2 < 2; n2++) {
                int krow = ki + b_krow;
                int glog = wn * 4 + n2 * 2 + b_nsub;
                int gphy = glog ^ (krow & 15);
                ldsm4t(bfr[n2], cvta_s(&Bs[cur][krow][gphy * 8]));
            }
            #pragma unroll
            for (int mi = 0; mi < 4; mi++)
                #pragma unroll
                for (int nj = 0; nj < 4; nj++)
                    mma16816(acc[mi][nj], af[mi], &bfr[nj >> 1][(nj & 1) * 2]);
        }

        if (it + 1 < KT) {
            if (BF32) {
                *(uint4*)&Bs[nxt][bk0][bp0]      = rb0;
                *(uint4*)&Bs[nxt][bk0 + 16][bp1] = rb1;
            }
            CP_WAIT0();
        }
        __syncthreads();
    }

    const int gid = lane >> 2, tig = lane & 3;
    #pragma unroll
    for (int mi = 0; mi < 4; mi++) {
        int m = m0 + wm * 64 + mi * 16 + gid;
        if (EPI == 0) {
            __nv_bfloat16* C0 = outb + (size_t)b * strideC + (size_t)m * NPIX;
            __nv_bfloat16* C1 = C0 + 8 * NPIX;
            #pragma unroll
            for (int nj = 0; nj < 4; nj++) {
                int n = n0 + wn * 32 + nj * 8 + tig * 2;
                __nv_bfloat162 lo = __floats2bfloat162_rn(acc[mi][nj][0], acc[mi][nj][1]);
                __nv_bfloat162 hi = __floats2bfloat162_rn(acc[mi][nj][2], acc[mi][nj][3]);
                *(__nv_bfloat162*)(C0 + n) = lo;
                *(__nv_bfloat162*)(C1 + n) = hi;
            }
        } else {
            const float g0 = gamma[m], g1 = gamma[m + 8];
            const float bo0 = bias[m], bo1 = bias[m + 8];
            float*       C0 = outf + (size_t)b * strideC + (size_t)m * NPIX;
            float*       C1 = C0 + 8 * NPIX;
            const float* X0 = xres + (size_t)b * strideC + (size_t)m * NPIX;
            const float* X1 = X0 + 8 * NPIX;
            #pragma unroll
            for (int nj = 0; nj < 4; nj++) {
                int n = n0 + wn * 32 + nj * 8 + tig * 2;
                float2 x0 = *(const float2*)(X0 + n);
                float2 x1 = *(const float2*)(X1 + n);
                float2 o0, o1;
                o0.x = fmaf(g0, acc[mi][nj][0] + bo0, x0.x);
                o0.y = fmaf(g0, acc[mi][nj][1] + bo0, x0.y);
                o1.x = fmaf(g1, acc[mi][nj][2] + bo1, x1.x);
                o1.y = fmaf(g1, acc[mi][nj][3] + bo1, x1.y);
                *(float2*)(C0 + n) = o0;
                *(float2*)(C1 + n) = o1;
            }
        }
    }

    // ---- fused exp-row-sum partials for the K rows (softmax denominator) ----
    if (KSTAT) {
        if (m0 >= 256 && m0 < 512) {           // uniform across block
            __shared__ float sden[4][128];
            #pragma unroll
            for (int mi = 0; mi < 4; mi++) {
                #pragma unroll
                for (int half = 0; half < 2; half++) {
                    float s = 0.f;
                    #pragma unroll
                    for (int nj = 0; nj < 4; nj++) {
                        s += __expf(acc[mi][nj][half * 2 + 0]);
                        s += __expf(acc[mi][nj][half * 2 + 1]);
                    }
                    s += __shfl_xor_sync(~0u, s, 1);
                    s += __shfl_xor_sync(~0u, s, 2);
                    if (tig == 0)
                        sden[wn][wm * 64 + mi * 16 + half * 8 + gid] = s;
                }
            }
            __syncthreads();
            if (t < 128) {
                float v = sden[0][t] + sden[1][t] + sden[2][t] + sden[3][t];
                denp[(size_t)blockIdx.x * (BATCH * 256) + b * 256 + (m0 - 256) + t] = v;
            }
        }
    }
}

// ============================================================================
// denominator reduce: dinv[r] = 1 / sum_nt denp[nt][r]
// ============================================================================
__global__ __launch_bounds__(256)
void k_dred(const float* __restrict__ denp, float* __restrict__ dinv)
{
    int i = blockIdx.x * 256 + threadIdx.x;      // 0 .. BATCH*256-1
    float s = 0.f;
    #pragma unroll
    for (int nt = 0; nt < NTIL; nt++)
        s += denp[(size_t)nt * (BATCH * 256) + i];
    dinv[i] = 1.0f / s;
}

// ============================================================================
// ctx partial (fused exp, no shift): ctxp[b,h,s][d][e] = sum_n exp(K[d,n]) V[e,n]
// NSPL=16, BK=64, double-buffered; V via cp.async, K via register+exp.
// ============================================================================
__global__ void __launch_bounds__(128)
ctx_mma(const __nv_bfloat16* __restrict__ qkv, float* __restrict__ ctxp)
{
    __shared__ __nv_bfloat16 Ks[2][64][72];
    __shared__ __nv_bfloat16 Vs[2][64][72];

    const int s = blockIdx.x, h = blockIdx.y, b = blockIdx.z;
    const int t = threadIdx.x, lane = t & 31, w = t >> 5;
    const int wm = w >> 1, wn = w & 1;
    const int NPER = NPIX / NSPL;       // 256

    const __nv_bfloat16* kb = qkv + ((size_t)b * O3 + 256 + h * DH) * NPIX + s * NPER;
    const __nv_bfloat16* vb = qkv + ((size_t)b * O3 + 512 + h * DH) * NPIX + s * NPER;

    const int scol = (t & 7) * 8;
    int srow[4];
    #pragma unroll
    for (int i = 0; i < 4; i++) srow[i] = (i * 128 + t) >> 3;

    float acc[2][4][4];
    #pragma unroll
    for (int i = 0; i < 2; i++)
        #pragma unroll
        for (int j = 0; j < 4; j++)
            #pragma unroll
            for (int c = 0; c < 4; c++) acc[i][j][c] = 0.f;

    const int a_row = (lane & 7) + 8 * ((lane >> 3) & 1);
    const int a_kad = 8 * (lane >> 4);
    const int b_row = (lane & 7) + 8 * ((lane >> 4) & 1);
    const int b_kad = 8 * ((lane >> 3) & 1);

    uint4 rk[4];

    #pragma unroll
    for (int i = 0; i < 4; i++) {
        uint4 kv = *(const uint4*)(kb + (size_t)srow[i] * NPIX + scol);
        *(uint4*)&Ks[0][srow[i]][scol] = exp_u4(kv);
        cp16(cvta_s(&Vs[0][srow[i]][scol]), vb + (size_t)srow[i] * NPIX + scol);
    }
    CP_COMMIT();
    CP_WAIT0();
    __syncthreads();

    const int IT = NPER / 64;           // 4
    #pragma unroll 1
    for (int it = 0; it < IT; it++) {
        const int cur = it & 1, nxt = cur ^ 1;
        const int kN = (it + 1) * 64;
        if (it + 1 < IT) {
            #pragma unroll
            for (int i = 0; i < 4; i++) {
                cp16(cvta_s(&Vs[nxt][srow[i]][scol]), vb + (size_t)srow[i] * NPIX + kN + scol);
                rk[i] = *(const uint4*)(kb + (size_t)srow[i] * NPIX + kN + scol);
            }
            CP_COMMIT();
        }

        #pragma unroll
        for (int ki = 0; ki < 64; ki += 16) {
            uint32_t af[2][4], bfr[2][4];
            #pragma unroll
            for (int mi = 0; mi < 2; mi++)
                ldsm4(af[mi], cvta_s(&Ks[cur][wm * 32 + mi * 16 + a_row][ki + a_kad]));
            #pragma unroll
            for (int n2 = 0; n2 < 2; n2++)
                ldsm4(bfr[n2], cvta_s(&Vs[cur][wn * 32 + n2 * 16 + b_row][ki + b_kad]));
            #pragma unroll
            for (int mi = 0; mi < 2; mi++)
                #pragma unroll
                for (int nj = 0; nj < 4; nj++)
                    mma16816(acc[mi][nj], af[mi], &bfr[nj >> 1][(nj & 1) * 2]);
        }

        if (it + 1 < IT) {
            #pragma unroll
            for (int i = 0; i < 4; i++)
                *(uint4*)&Ks[nxt][srow[i]][scol] = exp_u4(rk[i]);
            CP_WAIT0();
        }
        __syncthreads();
    }

    const int gid = lane >> 2, tig = lane & 3;
    float* dst = ctxp + (((size_t)(b * HEADS + h) * NSPL + s)) * (DH * DH);
    #pragma unroll
    for (int mi = 0; mi < 2; mi++) {
        int d = wm * 32 + mi * 16 + gid;
        #pragma unroll
        for (int nj = 0; nj < 4; nj++) {
            int e = wn * 32 + nj * 8 + tig * 2;
            *(float2*)(dst + (size_t)d * DH + e)       = make_float2(acc[mi][nj][0], acc[mi][nj][1]);
            *(float2*)(dst + (size_t)(d + 8) * DH + e) = make_float2(acc[mi][nj][2], acc[mi][nj][3]);
        }
    }
}

// ============================================================================
// small kernels
// ============================================================================
__global__ __launch_bounds__(256) void k_convw(const float* __restrict__ in,
                                               __nv_bfloat16* __restrict__ out) {
    int i = blockIdx.x * 256 + threadIdx.x;
    out[i] = __float2bfloat16(in[i]);
}

// Weff[b,o,h*64+d] = sum_e w_out[o,h*64+e] * (sum_s ctxp)[d][e] * dinv[d]
__global__ __launch_bounds__(256) void k_weff(const float* __restrict__ ctxp,
                                              const float* __restrict__ dinv,
                                              const float* __restrict__ w_out,
                                              __nv_bfloat16* __restrict__ weff) {
    __shared__ float cs[64][65];
    int bh = blockIdx.x, b = bh >> 2, h = bh & 3;
    int t = threadIdx.x;

    const float* cp = ctxp + ((size_t)bh * NSPL) * (DH * DH);
    #pragma unroll
    for (int i = 0; i < 16; i++) {
        int idx = i * 256 + t, d = idx >> 6, e = idx & 63;
        float v = 0.f;
        #pragma unroll
        for (int sp = 0; sp < NSPL; sp++) v += cp[(size_t)sp * (DH * DH) + idx];
        cs[d][e] = v * dinv[b * 256 + h * DH + d];
    }
    __syncthreads();

    int o = t;
    float wrow[64];
    const float4* wp = (const float4*)(w_out + (size_t)o * CDIM + h * DH);
    #pragma unroll
    for (int i = 0; i < 16; i++) {
        float4 v = wp[i];
        wrow[i * 4] = v.x; wrow[i * 4 + 1] = v.y; wrow[i * 4 + 2] = v.z; wrow[i * 4 + 3] = v.w;
    }
    __nv_bfloat16* dst = weff + ((size_t)b * CDIM + o) * CDIM + h * DH;
    for (int d = 0; d < DH; d++) {
        float acc = 0.f;
        #pragma unroll 16
        for (int e = 0; e < DH; e++) acc = fmaf(wrow[e], cs[d][e], acc);
        dst[d] = __float2bfloat16(acc);
    }
}

// ============================================================================
// launch
// ============================================================================
extern "C" void kernel_launch(void* const* d_in, const int* in_sizes, int n_in,
                              void* d_out, int out_size)
{
    const float* x     = (const float*)d_in[0];
    const float* w_qkv = (const float*)d_in[1];
    const float* w_out = (const float*)d_in[2];
    const float* b_out = (const float*)d_in[3];
    const float* gamma = (const float*)d_in[4];
    float*       y     = (float*)d_out;

    void *pwb, *pqkv, *pdenp, *pdinv, *pctxp, *pweff;
    cudaGetSymbolAddress(&pwb,   g_wb);
    cudaGetSymbolAddress(&pqkv,  g_qkvb);
    cudaGetSymbolAddress(&pdenp, g_denp);
    cudaGetSymbolAddress(&pdinv, g_dinv);
    cudaGetSymbolAddress(&pctxp, g_ctxp);
    cudaGetSymbolAddress(&pweff, g_weff);
    __nv_bfloat16* wb   = (__nv_bfloat16*)pwb;
    __nv_bfloat16* qkvb = (__nv_bfloat16*)pqkv;
    float*         denp = (float*)pdenp;
    float*         dinv = (float*)pdinv;
    float*         ctxp = (float*)pctxp;
    __nv_bfloat16* weff = (__nv_bfloat16*)pweff;

    // 0) convert weights to bf16
    k_convw<<<(O3 * CDIM) / 256, 256>>>(w_qkv, wb);

    // 1) qkv = w_qkv @ x  + fused exp-row-sum partials for K rows
    gemm_mma<0, 1, 1><<<dim3(NPIX / 128, O3 / 128, BATCH), 256>>>(
        wb, 0, nullptr, x, (long)CDIM * NPIX,
        nullptr, qkvb, (long)O3 * NPIX, nullptr, nullptr, nullptr, denp);

    // 2) fold partials -> 1/sum per K row
    k_dred<<<(BATCH * 256) / 256, 256>>>(denp, dinv);

    // 3) ctx partials (exp(k), no shift) + Weff contraction (applies 1/sum)
    ctx_mma<<<dim3(NSPL, HEADS, BATCH), 128>>>(qkvb, ctxp);
    k_weff<<<BATCH * HEADS, 256>>>(ctxp, dinv, w_out, weff);

    // 4) y = gamma*(Weff @ q + b_out) + x
    gemm_mma<1, 0, 0><<<dim3(NPIX / 128, CDIM / 128, BATCH), 256>>>(
        weff, (long)CDIM * CDIM, qkvb, nullptr, (long)O3 * NPIX,
        y, nullptr, (long)CDIM * NPIX, b_out, gamma, x, nullptr);
}

// round 16
// speedup vs baseline: 1.1529x; 1.0636x over previous
#include <cuda_runtime.h>
#include <cuda_bf16.h>
#include <cstdint>

#define BATCH 16
#define CDIM  256
#define NPIX  4096
#define O3    768
#define O2    512           // K,V rows only
#define HEADS 4
#define DH    64
#define NSPL  16
#define NTIL  32            // n-tiles in GEMM1 (NPIX/128)

// ------------------------- scratch ------------------------------------------
__device__ __nv_bfloat16 g_wb  [O3 * CDIM];                       // w_qkv bf16 (all 768 rows)
__device__ __nv_bfloat16 g_qkvb[(size_t)BATCH * O2 * NPIX];       // [b][K(256);V(256)][n]
__device__ float         g_denp[NTIL][BATCH * 256];               // per-n-tile exp sums
__device__ float         g_dinv[BATCH * 256];                     // 1/sum_exp per K row
__device__ float         g_ctxp[BATCH * HEADS * NSPL * DH * DH];  // ctx partials
__device__ __nv_bfloat16 g_weff[BATCH * CDIM * CDIM];             // Weff [b][o][hd]
__device__ __nv_bfloat16 g_meff[BATCH * CDIM * CDIM];             // Meff [b][o][c]

// ------------------------- helpers ------------------------------------------
__device__ __forceinline__ uint32_t cvta_s(const void* p) {
    return (uint32_t)__cvta_generic_to_shared(p);
}
__device__ __forceinline__ void cp16(uint32_t smem, const void* g) {
    asm volatile("cp.async.cg.shared.global [%0], [%1], 16;" :: "r"(smem), "l"(g));
}
#define CP_COMMIT() asm volatile("cp.async.commit_group;" ::: "memory")
#define CP_WAIT0()  asm volatile("cp.async.wait_group 0;" ::: "memory")

__device__ __forceinline__ void ldsm4(uint32_t* r, uint32_t a) {
    asm volatile("ldmatrix.sync.aligned.m8n8.x4.shared.b16 {%0,%1,%2,%3},[%4];"
                 : "=r"(r[0]), "=r"(r[1]), "=r"(r[2]), "=r"(r[3]) : "r"(a));
}
__device__ __forceinline__ void ldsm4t(uint32_t* r, uint32_t a) {
    asm volatile("ldmatrix.sync.aligned.m8n8.x4.trans.shared.b16 {%0,%1,%2,%3},[%4];"
                 : "=r"(r[0]), "=r"(r[1]), "=r"(r[2]), "=r"(r[3]) : "r"(a));
}
__device__ __forceinline__ void mma16816(float* d, const uint32_t* a, const uint32_t* b) {
    asm volatile(
        "mma.sync.aligned.m16n8k16.row.col.f32.bf16.bf16.f32 "
        "{%0,%1,%2,%3},{%4,%5,%6,%7},{%8,%9},{%0,%1,%2,%3};"
        : "+f"(d[0]), "+f"(d[1]), "+f"(d[2]), "+f"(d[3])
        : "r"(a[0]), "r"(a[1]), "r"(a[2]), "r"(a[3]), "r"(b[0]), "r"(b[1]));
}
__device__ __forceinline__ uint4 cvt8_bf16(float4 lo, float4 hi) {
    __nv_bfloat162 p0 = __floats2bfloat162_rn(lo.x, lo.y);
    __nv_bfloat162 p1 = __floats2bfloat162_rn(lo.z, lo.w);
    __nv_bfloat162 p2 = __floats2bfloat162_rn(hi.x, hi.y);
    __nv_bfloat162 p3 = __floats2bfloat162_rn(hi.z, hi.w);
    uint4 r;
    r.x = *(uint32_t*)&p0; r.y = *(uint32_t*)&p1;
    r.z = *(uint32_t*)&p2; r.w = *(uint32_t*)&p3;
    return r;
}
// exp(k) without max-shift: k = W_qkv.x with unit-variance operands, |k| << 88.
__device__ __forceinline__ uint32_t exp_bf162(uint32_t wv) {
    __nv_bfloat162 h = *(__nv_bfloat162*)&wv;
    __nv_bfloat162 r = __floats2bfloat162_rn(__expf(__low2float(h)),
                                             __expf(__high2float(h)));
    return *(uint32_t*)&r;
}
__device__ __forceinline__ uint4 exp_u4(uint4 v) {
    uint4 r;
    r.x = exp_bf162(v.x); r.y = exp_bf162(v.y);
    r.z = exp_bf162(v.z); r.w = exp_bf162(v.w);
    return r;
}

// ============================================================================
// bf16 HMMA GEMM:  C[b][M][LDN] = A[b][M][256] @ B[b][256][LDN]
//   BM=128, BN=128, BK=32.  256 thr = 8 warps (2x4), warp tile 64x32.
//   cp.async staging (A always; B when bf16), double-buffered.
//   KSTAT=1: K-row tiles (m0 < 256) also emit per-n-tile exp-row-sum partials.
// EPI 0: bf16 out.  EPI 1: y = gamma[m]*(acc+bias[m]) + x  (fp32)
// ============================================================================
template <int EPI, int BF32, int KSTAT, int LDN>
__global__ void __launch_bounds__(256, 2)
gemm_mma(const __nv_bfloat16* __restrict__ A, long strideA,
         const __nv_bfloat16* __restrict__ Bb16, const float* __restrict__ Bf32,
         long strideB,
         float* __restrict__ outf, __nv_bfloat16* __restrict__ outb,
         long strideC,
         const float* __restrict__ bias, const float* __restrict__ gamma,
         const float* __restrict__ xres, float* __restrict__ denp)
{
    __shared__ __nv_bfloat16 As[2][128][40];
    __shared__ __nv_bfloat16 Bs[2][32][128];

    const int t = threadIdx.x, lane = t & 31, w = t >> 5;
    const int wm = w >> 2, wn = w & 3;
    const int b = blockIdx.z, m0 = blockIdx.y * 128, n0 = blockIdx.x * 128;

    const __nv_bfloat16* Ab = A + (size_t)b * strideA;
    const __nv_bfloat16* Bb = BF32 ? nullptr : (Bb16 + (size_t)b * strideB);
    const float*         Bf = BF32 ? (Bf32 + (size_t)b * strideB) : nullptr;

    float acc[4][4][4];
    #pragma unroll
    for (int i = 0; i < 4; i++)
        #pragma unroll
        for (int j = 0; j < 4; j++)
            #pragma unroll
            for (int c = 0; c < 4; c++) acc[i][j][c] = 0.f;

    const int am0 = t >> 2, akg = (t & 3) * 8;
    const int bk0 = t >> 4, bng = t & 15;
    const int bp0 = (bng ^ (bk0 & 15)) * 8;
    const int bp1 = (bng ^ ((bk0 + 16) & 15)) * 8;

    const int a_row = (lane & 7) + 8 * ((lane >> 3) & 1);
    const int a_kad = 8 * (lane >> 4);
    const int b_krow = lane & 15;
    const int b_nsub = lane >> 4;

    uint4 rb0, rb1;

    cp16(cvta_s(&As[0][am0][akg]),      Ab + (size_t)(m0 + am0) * CDIM + akg);
    cp16(cvta_s(&As[0][am0 + 64][akg]), Ab + (size_t)(m0 + am0 + 64) * CDIM + akg);
    if (BF32) {
        const float* r0 = Bf + (size_t)bk0 * LDN + n0 + bng * 8;
        const float* r1 = Bf + (size_t)(bk0 + 16) * LDN + n0 + bng * 8;
        rb0 = cvt8_bf16(*(const float4*)r0, *(const float4*)(r0 + 4));
        rb1 = cvt8_bf16(*(const float4*)r1, *(const float4*)(r1 + 4));
        *(uint4*)&Bs[0][bk0][bp0]      = rb0;
        *(uint4*)&Bs[0][bk0 + 16][bp1] = rb1;
    } else {
        cp16(cvta_s(&Bs[0][bk0][bp0]),      Bb + (size_t)bk0 * LDN + n0 + bng * 8);
        cp16(cvta_s(&Bs[0][bk0 + 16][bp1]), Bb + (size_t)(bk0 + 16) * LDN + n0 + bng * 8);
    }
    CP_COMMIT();
    CP_WAIT0();
    __syncthreads();

    const int KT = CDIM / 32;
    #pragma unroll 1
    for (int it = 0; it < KT; it++) {
        const int cur = it & 1, nxt = cur ^ 1;
        const int kN = (it + 1) * 32;
        if (it + 1 < KT) {
            cp16(cvta_s(&As[nxt][am0][akg]),      Ab + (size_t)(m0 + am0) * CDIM + kN + akg);
            cp16(cvta_s(&As[nxt][am0 + 64][akg]), Ab + (size_t)(m0 + am0 + 64) * CDIM + kN + akg);
            if (BF32) {
                const float* r0 = Bf + (size_t)(kN + bk0) * LDN + n0 + bng * 8;
                const float* r1 = Bf + (size_t)(kN + bk0 + 16) * LDN + n0 + bng * 8;
                rb0 = cvt8_bf16(*(const float4*)r0, *(const float4*)(r0 + 4));
                rb1 = cvt8_bf16(*(const float4*)r1, *(const float4*)(r1 + 4));
            } else {
                cp16(cvta_s(&Bs[nxt][bk0][bp0]),      Bb + (size_t)(kN + bk0) * LDN + n0 + bng * 8);
                cp16(cvta_s(&Bs[nxt][bk0 + 16][bp1]), Bb + (size_t)(kN + bk0 + 16) * LDN + n0 + bng * 8);
            }
            CP_COMMIT();
        }

        #pragma unroll
        for (int ki = 0; ki < 32; ki += 16) {
            uint32_t af[4][4], bfr[2][4];
            #pragma unroll
            for (int mi = 0; mi < 4; mi++)
                ldsm4(af[mi], cvta_s(&As[cur][wm * 64 + mi * 16 + a_row][ki + a_kad]));
            #pragma unroll
            for (int n2 = 0; n2 < 2; n2++) {
                int krow = ki + b_krow;
                int glog = wn * 4 + n2 * 2 + b_nsub;
                int gphy = glog ^ (krow & 15);
                ldsm4t(bfr[n2], cvta_s(&Bs[cur][krow][gphy * 8]));
            }
            #pragma unroll
            for (int mi = 0; mi < 4; mi++)
                #pragma unroll
                for (int nj = 0; nj < 4; nj++)
                    mma16816(acc[mi][nj], af[mi], &bfr[nj >> 1][(nj & 1) * 2]);
        }

        if (it + 1 < KT) {
            if (BF32) {
                *(uint4*)&Bs[nxt][bk0][bp0]      = rb0;
                *(uint4*)&Bs[nxt][bk0 + 16][bp1] = rb1;
            }
            CP_WAIT0();
        }
        __syncthreads();
    }

    const int gid = lane >> 2, tig = lane & 3;
    #pragma unroll
    for (int mi = 0; mi < 4; mi++) {
        int m = m0 + wm * 64 + mi * 16 + gid;
        if (EPI == 0) {
            __nv_bfloat16* C0 = outb + (size_t)b * strideC + (size_t)m * LDN;
            __nv_bfloat16* C1 = C0 + 8 * LDN;
            #pragma unroll
            for (int nj = 0; nj < 4; nj++) {
                int n = n0 + wn * 32 + nj * 8 + tig * 2;
                __nv_bfloat162 lo = __floats2bfloat162_rn(acc[mi][nj][0], acc[mi][nj][1]);
                __nv_bfloat162 hi = __floats2bfloat162_rn(acc[mi][nj][2], acc[mi][nj][3]);
                *(__nv_bfloat162*)(C0 + n) = lo;
                *(__nv_bfloat162*)(C1 + n) = hi;
            }
        } else {
            const float g0 = gamma[m], g1 = gamma[m + 8];
            const float bo0 = bias[m], bo1 = bias[m + 8];
            float*       C0 = outf + (size_t)b * strideC + (size_t)m * LDN;
            float*       C1 = C0 + 8 * LDN;
            const float* X0 = xres + (size_t)b * strideC + (size_t)m * LDN;
            const float* X1 = X0 + 8 * LDN;
            #pragma unroll
            for (int nj = 0; nj < 4; nj++) {
                int n = n0 + wn * 32 + nj * 8 + tig * 2;
                float2 x0 = *(const float2*)(X0 + n);
                float2 x1 = *(const float2*)(X1 + n);
                float2 o0, o1;
                o0.x = fmaf(g0, acc[mi][nj][0] + bo0, x0.x);
                o0.y = fmaf(g0, acc[mi][nj][1] + bo0, x0.y);
                o1.x = fmaf(g1, acc[mi][nj][2] + bo1, x1.x);
                o1.y = fmaf(g1, acc[mi][nj][3] + bo1, x1.y);
                *(float2*)(C0 + n) = o0;
                *(float2*)(C1 + n) = o1;
            }
        }
    }

    // ---- fused exp-row-sum partials for K rows (now rows 0..255) ----
    if (KSTAT) {
        if (m0 < 256) {
            __shared__ float sden[4][128];
            #pragma unroll
            for (int mi = 0; mi < 4; mi++) {
                #pragma unroll
                for (int half = 0; half < 2; half++) {
                    float s = 0.f;
                    #pragma unroll
                    for (int nj = 0; nj < 4; nj++) {
                        s += __expf(acc[mi][nj][half * 2 + 0]);
                        s += __expf(acc[mi][nj][half * 2 + 1]);
                    }
                    s += __shfl_xor_sync(~0u, s, 1);
                    s += __shfl_xor_sync(~0u, s, 2);
                    if (tig == 0)
                        sden[wn][wm * 64 + mi * 16 + half * 8 + gid] = s;
                }
            }
            __syncthreads();
            if (t < 128) {
                float v = sden[0][t] + sden[1][t] + sden[2][t] + sden[3][t];
                denp[(size_t)blockIdx.x * (BATCH * 256) + b * 256 + m0 + t] = v;
            }
        }
    }
}

// ============================================================================
// denominator reduce: dinv[r] = 1 / sum_nt denp[nt][r]
// ============================================================================
__global__ __launch_bounds__(256)
void k_dred(const float* __restrict__ denp, float* __restrict__ dinv)
{
    int i = blockIdx.x * 256 + threadIdx.x;
    float s = 0.f;
    #pragma unroll
    for (int nt = 0; nt < NTIL; nt++)
        s += denp[(size_t)nt * (BATCH * 256) + i];
    dinv[i] = 1.0f / s;
}

// ============================================================================
// ctx partial (fused exp): ctxp[b,h,s][d][e] = sum_n exp(K[d,n]) V[e,n]
// qkv layout now [b][K(0..255);V(256..511)][n].
// ============================================================================
__global__ void __launch_bounds__(128)
ctx_mma(const __nv_bfloat16* __restrict__ qkv, float* __restrict__ ctxp)
{
    __shared__ __nv_bfloat16 Ks[2][64][72];
    __shared__ __nv_bfloat16 Vs[2][64][72];

    const int s = blockIdx.x, h = blockIdx.y, b = blockIdx.z;
    const int t = threadIdx.x, lane = t & 31, w = t >> 5;
    const int wm = w >> 1, wn = w & 1;
    const int NPER = NPIX / NSPL;       // 256

    const __nv_bfloat16* kb = qkv + ((size_t)b * O2 + h * DH) * NPIX + s * NPER;
    const __nv_bfloat16* vb = qkv + ((size_t)b * O2 + 256 + h * DH) * NPIX + s * NPER;

    const int scol = (t & 7) * 8;
    int srow[4];
    #pragma unroll
    for (int i = 0; i < 4; i++) srow[i] = (i * 128 + t) >> 3;

    float acc[2][4][4];
    #pragma unroll
    for (int i = 0; i < 2; i++)
        #pragma unroll
        for (int j = 0; j < 4; j++)
            #pragma unroll
            for (int c = 0; c < 4; c++) acc[i][j][c] = 0.f;

    const int a_row = (lane & 7) + 8 * ((lane >> 3) & 1);
    const int a_kad = 8 * (lane >> 4);
    const int b_row = (lane & 7) + 8 * ((lane >> 4) & 1);
    const int b_kad = 8 * ((lane >> 3) & 1);

    uint4 rk[4];

    #pragma unroll
    for (int i = 0; i < 4; i++) {
        uint4 kv = *(const uint4*)(kb + (size_t)srow[i] * NPIX + scol);
        *(uint4*)&Ks[0][srow[i]][scol] = exp_u4(kv);
        cp16(cvta_s(&Vs[0][srow[i]][scol]), vb + (size_t)srow[i] * NPIX + scol);
    }
    CP_COMMIT();
    CP_WAIT0();
    __syncthreads();

    const int IT = NPER / 64;           // 4
    #pragma unroll 1
    for (int it = 0; it < IT; it++) {
        const int cur = it & 1, nxt = cur ^ 1;
        const int kN = (it + 1) * 64;
        if (it + 1 < IT) {
            #pragma unroll
            for (int i = 0; i < 4; i++) {
                cp16(cvta_s(&Vs[nxt][srow[i]][scol]), vb + (size_t)srow[i] * NPIX + kN + scol);
                rk[i] = *(const uint4*)(kb + (size_t)srow[i] * NPIX + kN + scol);
            }
            CP_COMMIT();
        }

        #pragma unroll
        for (int ki = 0; ki < 64; ki += 16) {
            uint32_t af[2][4], bfr[2][4];
            #pragma unroll
            for (int mi = 0; mi < 2; mi++)
                ldsm4(af[mi], cvta_s(&Ks[cur][wm * 32 + mi * 16 + a_row][ki + a_kad]));
            #pragma unroll
            for (int n2 = 0; n2 < 2; n2++)
                ldsm4(bfr[n2], cvta_s(&Vs[cur][wn * 32 + n2 * 16 + b_row][ki + b_kad]));
            #pragma unroll
            for (int mi = 0; mi < 2; mi++)
                #pragma unroll
                for (int nj = 0; nj < 4; nj++)
                    mma16816(acc[mi][nj], af[mi], &bfr[nj >> 1][(nj & 1) * 2]);
        }

        if (it + 1 < IT) {
            #pragma unroll
            for (int i = 0; i < 4; i++)
                *(uint4*)&Ks[nxt][srow[i]][scol] = exp_u4(rk[i]);
            CP_WAIT0();
        }
        __syncthreads();
    }

    const int gid = lane >> 2, tig = lane & 3;
    float* dst = ctxp + (((size_t)(b * HEADS + h) * NSPL + s)) * (DH * DH);
    #pragma unroll
    for (int mi = 0; mi < 2; mi++) {
        int d = wm * 32 + mi * 16 + gid;
        #pragma unroll
        for (int nj = 0; nj < 4; nj++) {
            int e = wn * 32 + nj * 8 + tig * 2;
            *(float2*)(dst + (size_t)d * DH + e)       = make_float2(acc[mi][nj][0], acc[mi][nj][1]);
            *(float2*)(dst + (size_t)(d + 8) * DH + e) = make_float2(acc[mi][nj][2], acc[mi][nj][3]);
        }
    }
}

// ============================================================================
// small kernels
// ============================================================================
__global__ __launch_bounds__(256) void k_convw(const float* __restrict__ in,
                                               __nv_bfloat16* __restrict__ out) {
    int i = blockIdx.x * 256 + threadIdx.x;
    out[i] = __float2bfloat16(in[i]);
}

// Weff[b,o,h*64+d] = sum_e w_out[o,h*64+e] * (sum_s ctxp)[d][e] * dinv[d]
__global__ __launch_bounds__(256) void k_weff(const float* __restrict__ ctxp,
                                              const float* __restrict__ dinv,
                                              const float* __restrict__ w_out,
                                              __nv_bfloat16* __restrict__ weff) {
    __shared__ float cs[64][65];
    int bh = blockIdx.x, b = bh >> 2, h = bh & 3;
    int t = threadIdx.x;

    const float* cp = ctxp + ((size_t)bh * NSPL) * (DH * DH);
    #pragma unroll
    for (int i = 0; i < 16; i++) {
        int idx = i * 256 + t, d = idx >> 6, e = idx & 63;
        float v = 0.f;
        #pragma unroll
        for (int sp = 0; sp < NSPL; sp++) v += cp[(size_t)sp * (DH * DH) + idx];
        cs[d][e] = v * dinv[b * 256 + h * DH + d];
    }
    __syncthreads();

    int o = t;
    float wrow[64];
    const float4* wp = (const float4*)(w_out + (size_t)o * CDIM + h * DH);
    #pragma unroll
    for (int i = 0; i < 16; i++) {
        float4 v = wp[i];
        wrow[i * 4] = v.x; wrow[i * 4 + 1] = v.y; wrow[i * 4 + 2] = v.z; wrow[i * 4 + 3] = v.w;
    }
    __nv_bfloat16* dst = weff + ((size_t)b * CDIM + o) * CDIM + h * DH;
    for (int d = 0; d < DH; d++) {
        float acc = 0.f;
        #pragma unroll 16
        for (int e = 0; e < DH; e++) acc = fmaf(wrow[e], cs[d][e], acc);
        dst[d] = __float2bfloat16(acc);
    }
}

// ============================================================================
// launch
// ============================================================================
extern "C" void kernel_launch(void* const* d_in, const int* in_sizes, int n_in,
                              void* d_out, int out_size)
{
    const float* x     = (const float*)d_in[0];
    const float* w_qkv = (const float*)d_in[1];
    const float* w_out = (const float*)d_in[2];
    const float* b_out = (const float*)d_in[3];
    const float* gamma = (const float*)d_in[4];
    float*       y     = (float*)d_out;

    void *pwb, *pqkv, *pdenp, *pdinv, *pctxp, *pweff, *pmeff;
    cudaGetSymbolAddress(&pwb,   g_wb);
    cudaGetSymbolAddress(&pqkv,  g_qkvb);
    cudaGetSymbolAddress(&pdenp, g_denp);
    cudaGetSymbolAddress(&pdinv, g_dinv);
    cudaGetSymbolAddress(&pctxp, g_ctxp);
    cudaGetSymbolAddress(&pweff, g_weff);
    cudaGetSymbolAddress(&pmeff, g_meff);
    __nv_bfloat16* wb   = (__nv_bfloat16*)pwb;
    __nv_bfloat16* qkvb = (__nv_bfloat16*)pqkv;
    float*         denp = (float*)pdenp;
    float*         dinv = (float*)pdinv;
    float*         ctxp = (float*)pctxp;
    __nv_bfloat16* weff = (__nv_bfloat16*)pweff;
    __nv_bfloat16* meff = (__nv_bfloat16*)pmeff;

    // 0) convert all w_qkv to bf16 (q rows used by Meff GEMM; k,v rows by GEMM1)
    k_convw<<<(O3 * CDIM) / 256, 256>>>(w_qkv, wb);

    // 1) [k;v] = w_qkv[256:768] @ x  + fused exp-row-sum partials for K rows
    gemm_mma<0, 1, 1, NPIX><<<dim3(NPIX / 128, O2 / 128, BATCH), 256>>>(
        wb + 256 * CDIM, 0, nullptr, x, (long)CDIM * NPIX,
        nullptr, qkvb, (long)O2 * NPIX, nullptr, nullptr, nullptr, denp);

    // 2) fold partials -> 1/sum per K row
    k_dred<<<(BATCH * 256) / 256, 256>>>(denp, dinv);

    // 3) ctx partials + Weff = w_out-contracted normalized context
    ctx_mma<<<dim3(NSPL, HEADS, BATCH), 128>>>(qkvb, ctxp);
    k_weff<<<BATCH * HEADS, 256>>>(ctxp, dinv, w_out, weff);

    // 4) Meff_b = Weff_b @ W_q   (256x256x256 per batch; q never materialized)
    gemm_mma<0, 0, 0, CDIM><<<dim3(2, 2, BATCH), 256>>>(
        weff, (long)CDIM * CDIM, wb, nullptr, 0,
        nullptr, meff, (long)CDIM * CDIM, nullptr, nullptr, nullptr, nullptr);

    // 5) y = gamma*(Meff_b @ x + b_out) + x
    gemm_mma<1, 1, 0, NPIX><<<dim3(NPIX / 128, CDIM / 128, BATCH), 256>>>(
        meff, (long)CDIM * CDIM, nullptr, x, (long)CDIM * NPIX,
        y, nullptr, (long)CDIM * NPIX, b_out, gamma, x, nullptr);
}